// round 1
// baseline (speedup 1.0000x reference)
#include <cuda_runtime.h>
#include <cuda_bf16.h>
#include <math.h>

// Problem constants
#define B_    4
#define SEQ_  2048
#define DIM_  1024
#define HD_   128
#define NH_   8
#define SCALE_ 0.088388347648318447f   // 1/sqrt(128)

// ---------------- scratch (static device globals; no allocation) -----------
__device__ float g_Qh[(size_t)B_*NH_*SEQ_*HD_];   // per-head projected Q=K=V, [b][h][s][d]
__device__ float g_u [(size_t)B_*NH_*SEQ_*HD_];   // backward scan state u[t] = Q[t] + gamma*u[t+1]
__device__ float g_gate[(size_t)B_*SEQ_*DIM_];    // swish(q@Wg+bg)
__device__ float g_ho[(size_t)B_*NH_*SEQ_*HD_];   // retention head outputs
__device__ float g_Z [(size_t)B_*SEQ_*DIM_];      // gate * groupnorm(x)
__device__ float g_gpow[NH_*(SEQ_+1)];            // gamma^d tables
__device__ float g_rD  [NH_*SEQ_];                // 1/sqrt(colsum(D))[t]
__device__ float g_coef[B_*NH_*SEQ_];             // rD[t]/max(|cs[t]|,1)

// ---------------- decay tables ---------------------------------------------
__global__ void k_decay() {
    int h = threadIdx.x;
    if (h >= NH_) return;
    double gamma = 1.0 - exp2(-5.0 - (double)h);
    double p = 1.0;
    for (int d = 0; d <= SEQ_; d++) { g_gpow[h*(SEQ_+1)+d] = (float)p; p *= gamma; }
    double lg = log(gamma);
    double om = 1.0 - gamma;
    for (int t = 0; t < SEQ_; t++) {
        double denom = 1.0 - exp((double)(SEQ_-t)*lg);   // 1 - gamma^(S-t)
        g_rD[h*SEQ_+t] = (float)sqrt(om/denom);
    }
}

// ---------------- per-head projection: Qh = q_head @ W_qkv[h] ---------------
// grid (SEQ/64, B*NH), 256 threads; tile 64x128, K=128 chunked by 16
__global__ __launch_bounds__(256)
void k_proj(const float* __restrict__ q, const float* __restrict__ Wq) {
    int bh = blockIdx.y;
    int b = bh / NH_, h = bh % NH_;
    int s0 = blockIdx.x * 64;
    __shared__ float As[16][64];
    __shared__ float Bs[16][132];
    int tid = threadIdx.x;
    int tx = tid & 15, ty = tid >> 4;            // cols tx*8, rows ty*4
    float acc[4][8];
    #pragma unroll
    for (int i=0;i<4;i++) for (int j=0;j<8;j++) acc[i][j]=0.f;

    const float* A  = q  + (size_t)b*SEQ_*DIM_ + h*HD_;
    const float* Bm = Wq + (size_t)h*HD_*HD_;

    for (int k0 = 0; k0 < HD_; k0 += 16) {
        {   // A tile 64x16 -> transposed
            int row = tid >> 2, qd = (tid & 3) << 2;
            float4 v = *(const float4*)(A + (size_t)(s0+row)*DIM_ + k0 + qd);
            As[qd+0][row]=v.x; As[qd+1][row]=v.y; As[qd+2][row]=v.z; As[qd+3][row]=v.w;
        }
        #pragma unroll
        for (int i = 0; i < 2; i++) {   // B tile 16x128
            int idx = tid + i*256;
            int k = idx >> 5, c4 = (idx & 31) << 2;
            float4 v = *(const float4*)(Bm + (size_t)(k0+k)*HD_ + c4);
            *(float4*)&Bs[k][c4] = v;
        }
        __syncthreads();
        #pragma unroll
        for (int kk = 0; kk < 16; kk++) {
            float a[4], bb[8];
            #pragma unroll
            for (int i=0;i<4;i++) a[i] = As[kk][ty*4+i];
            #pragma unroll
            for (int j=0;j<8;j++) bb[j] = Bs[kk][tx*8+j];
            #pragma unroll
            for (int i=0;i<4;i++)
                #pragma unroll
                for (int j=0;j<8;j++) acc[i][j] = fmaf(a[i], bb[j], acc[i][j]);
        }
        __syncthreads();
    }
    float* outp = g_Qh + ((size_t)bh*SEQ_ + s0)*HD_;
    #pragma unroll
    for (int i=0;i<4;i++)
        #pragma unroll
        for (int j=0;j<8;j+=4) {
            float4 v = make_float4(acc[i][j],acc[i][j+1],acc[i][j+2],acc[i][j+3]);
            *(float4*)(outp + (size_t)(ty*4+i)*HD_ + tx*8 + j) = v;
        }
}

// ---------------- generic 1024-K GEMM: C = epi(A@B + bias) ------------------
// MODE 0: swish epilogue (gate); MODE 1: plain bias epilogue (final output)
template<int MODE>
__global__ __launch_bounds__(256)
void k_gemm1024(const float* __restrict__ A, const float* __restrict__ Bm,
                const float* __restrict__ bias, float* __restrict__ C) {
    const int K = DIM_, N = DIM_;
    int n0 = blockIdx.x * 128, m0 = blockIdx.y * 128;
    __shared__ float As[8][128];
    __shared__ float Bs[8][132];
    int tid = threadIdx.x;
    int tx = tid & 15, ty = tid >> 4;
    float acc[8][8];
    #pragma unroll
    for (int i=0;i<8;i++) for (int j=0;j<8;j++) acc[i][j]=0.f;

    for (int k0 = 0; k0 < K; k0 += 8) {
        {
            int row = tid >> 1, qq = (tid & 1) << 2;
            float4 v = *(const float4*)(A + (size_t)(m0+row)*K + k0 + qq);
            As[qq+0][row]=v.x; As[qq+1][row]=v.y; As[qq+2][row]=v.z; As[qq+3][row]=v.w;
        }
        {
            int k = tid >> 5, c4 = (tid & 31) << 2;
            float4 v = *(const float4*)(Bm + (size_t)(k0+k)*N + n0 + c4);
            *(float4*)&Bs[k][c4] = v;
        }
        __syncthreads();
        #pragma unroll
        for (int kk = 0; kk < 8; kk++) {
            float a[8], bb[8];
            #pragma unroll
            for (int i=0;i<8;i++) a[i] = As[kk][ty*8+i];
            #pragma unroll
            for (int j=0;j<8;j++) bb[j] = Bs[kk][tx*8+j];
            #pragma unroll
            for (int i=0;i<8;i++)
                #pragma unroll
                for (int j=0;j<8;j++) acc[i][j] = fmaf(a[i], bb[j], acc[i][j]);
        }
        __syncthreads();
    }
    #pragma unroll
    for (int i=0;i<8;i++) {
        int row = m0 + ty*8 + i;
        #pragma unroll
        for (int j=0;j<8;j+=4) {
            int col = n0 + tx*8 + j;
            float4 bsv = *(const float4*)(bias + col);
            float4 v;
            v.x = acc[i][j+0] + bsv.x;
            v.y = acc[i][j+1] + bsv.y;
            v.z = acc[i][j+2] + bsv.z;
            v.w = acc[i][j+3] + bsv.w;
            if (MODE == 0) {   // swish
                v.x = v.x / (1.f + __expf(-v.x));
                v.y = v.y / (1.f + __expf(-v.y));
                v.z = v.z / (1.f + __expf(-v.z));
                v.w = v.w / (1.f + __expf(-v.w));
            }
            *(float4*)(C + (size_t)row*N + col) = v;
        }
    }
}

// ---------------- backward linear scan: u[t] = Q[t] + gamma*u[t+1] ----------
// grid B*NH, 128 threads (one per head dim)
__global__ void k_scan() {
    int bh = blockIdx.x;
    int h = bh % NH_;
    int d = threadIdx.x;
    float gamma = 1.f - exp2f(-5.f - (float)h);
    const float* Q = g_Qh + (size_t)bh*SEQ_*HD_ + d;
    float* U = g_u + (size_t)bh*SEQ_*HD_ + d;
    float u = 0.f;
    for (int t = SEQ_-1; t >= 0; t--) {
        u = fmaf(gamma, u, Q[(size_t)t*HD_]);
        U[(size_t)t*HD_] = u;
    }
}

// ---------------- coef[t] = rD[t] / max(|rD[t]*scale*Q[t].u[t]|, 1) ---------
// one warp per (b,h,t)
__global__ void k_coef() {
    int gw   = blockIdx.x * 8 + (threadIdx.x >> 5);
    int lane = threadIdx.x & 31;
    int bh = gw >> 11;          // / SEQ_
    int t  = gw & (SEQ_-1);
    const float* Q = g_Qh + ((size_t)bh*SEQ_ + t)*HD_;
    const float* U = g_u  + ((size_t)bh*SEQ_ + t)*HD_;
    float s = 0.f;
    #pragma unroll
    for (int i = lane; i < HD_; i += 32) s = fmaf(Q[i], U[i], s);
    #pragma unroll
    for (int o = 16; o; o >>= 1) s += __shfl_xor_sync(0xffffffffu, s, o);
    if (lane == 0) {
        int h = bh % NH_;
        float rd  = g_rD[h*SEQ_ + t];
        float cs  = rd * (s * SCALE_);
        g_coef[bh*SEQ_ + t] = rd / fmaxf(fabsf(cs), 1.f);
    }
}

// ---------------- quadratic decayed-attention output pass -------------------
// out[s,:] = sum_{t<=s} scale*gamma^(s-t)*coef[t] * (Q[s].Q[t]) * Q[t,:]
// grid (SEQ/128, B*NH), 256 threads, dynamic smem 84.5KB
#define SM2_BYTES ((128*132 + 2*16*132) * 4)
__global__ __launch_bounds__(256, 1)
void k_pass2() {
    extern __shared__ float sm[];
    float* Ps = sm;                 // [128][132]
    float* As = sm + 128*132;       // [16][132]
    float* Bs = As + 16*132;        // [16][132], reused for V chunks
    const int tid = threadIdx.x;
    const int tx = tid & 15, ty = tid >> 4;
    const int bh = blockIdx.y;
    const int st = blockIdx.x;
    const int s0 = st * 128;
    const int h  = bh % NH_;
    const float* Qb = g_Qh  + (size_t)bh * SEQ_ * HD_;
    const float* gp = g_gpow + h * (SEQ_+1);
    const float* cf = g_coef + bh * SEQ_;

    // decay factorization: gamma^(s-t) = gamma^(s0-t0) * gamma^(s-s0) / gamma^(t-t0)
    float rowf[8], cinv[8];
    #pragma unroll
    for (int i=0;i<8;i++) rowf[i] = gp[ty*8+i];
    #pragma unroll
    for (int j=0;j<8;j++) cinv[j] = 1.f / gp[tx*8+j];

    float O[8][8];
    #pragma unroll
    for (int i=0;i<8;i++) for (int j=0;j<8;j++) O[i][j]=0.f;

    for (int tt = 0; tt <= st; tt++) {
        const int t0 = tt * 128;
        float S[8][8];
        #pragma unroll
        for (int i=0;i<8;i++) for (int j=0;j<8;j++) S[i][j]=0.f;

        // ---- stage a: S = Q_s @ Q_t^T (K chunked by 16) ----
        for (int k0 = 0; k0 < HD_; k0 += 16) {
            #pragma unroll
            for (int i=0;i<2;i++) {
                int idx = tid + i*256;
                int row = idx >> 2;
                int qq  = (idx & 3) << 2;
                float4 va = *(const float4*)(Qb + (size_t)(s0+row)*HD_ + k0 + qq);
                As[(qq+0)*132+row]=va.x; As[(qq+1)*132+row]=va.y;
                As[(qq+2)*132+row]=va.z; As[(qq+3)*132+row]=va.w;
                float4 vb = *(const float4*)(Qb + (size_t)(t0+row)*HD_ + k0 + qq);
                Bs[(qq+0)*132+row]=vb.x; Bs[(qq+1)*132+row]=vb.y;
                Bs[(qq+2)*132+row]=vb.z; Bs[(qq+3)*132+row]=vb.w;
            }
            __syncthreads();
            #pragma unroll
            for (int kk=0; kk<16; kk++) {
                float a[8], b[8];
                #pragma unroll
                for (int i=0;i<8;i++) a[i] = As[kk*132 + ty*8 + i];
                #pragma unroll
                for (int j=0;j<8;j++) b[j] = Bs[kk*132 + tx*8 + j];
                #pragma unroll
                for (int i=0;i<8;i++)
                    #pragma unroll
                    for (int j=0;j<8;j++) S[i][j] = fmaf(a[i], b[j], S[i][j]);
            }
            __syncthreads();
        }

        // ---- stage b: apply decay/mask/coef, write P to smem ----
        float tf = SCALE_ * gp[s0 - t0];
        if (tt < st) {
            #pragma unroll
            for (int i=0;i<8;i++) {
                float rf = tf * rowf[i];
                #pragma unroll
                for (int j=0;j<8;j++) {
                    int t = t0 + tx*8 + j;
                    Ps[(ty*8+i)*132 + tx*8 + j] = S[i][j] * rf * cinv[j] * cf[t];
                }
            }
        } else {   // diagonal tile: mask s >= t
            #pragma unroll
            for (int i=0;i<8;i++) {
                int s = s0 + ty*8 + i;
                float rf = tf * rowf[i];
                #pragma unroll
                for (int j=0;j<8;j++) {
                    int t = t0 + tx*8 + j;
                    float w = (s >= t) ? (rf * cinv[j] * cf[t]) : 0.f;
                    Ps[(ty*8+i)*132 + tx*8 + j] = S[i][j] * w;
                }
            }
        }
        __syncthreads();

        // ---- stage c: O += P @ V (V = Q rows of t-block), chunked by 16 ----
        for (int k0 = 0; k0 < 128; k0 += 16) {
            #pragma unroll
            for (int i=0;i<2;i++) {
                int idx = tid + i*256;
                int k  = idx >> 5;
                int c4 = (idx & 31) << 2;
                float4 v = *(const float4*)(Qb + (size_t)(t0+k0+k)*HD_ + c4);
                *(float4*)&Bs[k*132 + c4] = v;
            }
            __syncthreads();
            #pragma unroll
            for (int kk=0; kk<16; kk++) {
                float p[8], v[8];
                #pragma unroll
                for (int i=0;i<8;i++) p[i] = Ps[(ty*8+i)*132 + k0 + kk];
                #pragma unroll
                for (int j=0;j<8;j++) v[j] = Bs[kk*132 + tx*8 + j];
                #pragma unroll
                for (int i=0;i<8;i++)
                    #pragma unroll
                    for (int j=0;j<8;j++) O[i][j] = fmaf(p[i], v[j], O[i][j]);
            }
            __syncthreads();
        }
    }

    float* outp = g_ho + ((size_t)bh*SEQ_ + s0) * HD_;
    #pragma unroll
    for (int i=0;i<8;i++)
        #pragma unroll
        for (int j=0;j<8;j+=4) {
            float4 v = make_float4(O[i][j],O[i][j+1],O[i][j+2],O[i][j+3]);
            *(float4*)(outp + (size_t)(ty*8+i)*HD_ + tx*8 + j) = v;
        }
}

// ---------------- GroupNorm(32 groups) + beta, then gate --------------------
// one block per (b,s); 256 threads x 4 channels each; group = 32 channels = 8 threads
__global__ __launch_bounds__(256)
void k_gn(const float* __restrict__ beta) {
    int row = blockIdx.x;             // b*SEQ + s
    int b = row >> 11, s = row & (SEQ_-1);
    int tid = threadIdx.x;
    int c = tid << 2;
    int h = c >> 7, d = c & 127;
    float4 x = *(const float4*)(g_ho + (((size_t)(b*NH_+h)*SEQ_ + s)*HD_ + d));

    float sum = x.x + x.y + x.z + x.w;
    #pragma unroll
    for (int o = 1; o < 8; o <<= 1) sum += __shfl_xor_sync(0xffffffffu, sum, o);
    float mu = sum * (1.f/32.f);

    float dx0 = x.x-mu, dx1 = x.y-mu, dx2 = x.z-mu, dx3 = x.w-mu;
    float sq = dx0*dx0 + dx1*dx1 + dx2*dx2 + dx3*dx3;
    #pragma unroll
    for (int o = 1; o < 8; o <<= 1) sq += __shfl_xor_sync(0xffffffffu, sq, o);
    float inv = rsqrtf(sq * (1.f/32.f) + 1e-3f);

    float4 be = *(const float4*)(beta + c);
    float4 g  = *(const float4*)(g_gate + (size_t)row*DIM_ + c);
    float4 z;
    z.x = (dx0*inv + be.x) * g.x;
    z.y = (dx1*inv + be.y) * g.y;
    z.z = (dx2*inv + be.z) * g.z;
    z.w = (dx3*inv + be.w) * g.w;
    *(float4*)(g_Z + (size_t)row*DIM_ + c) = z;
}

// ---------------- launch ----------------------------------------------------
extern "C" void kernel_launch(void* const* d_in, const int* in_sizes, int n_in,
                              void* d_out, int out_size) {
    (void)in_sizes; (void)n_in; (void)out_size;
    const float* q    = (const float*)d_in[0];
    // d_in[1] = k, d_in[2] = v : unused by the reference (heads use q for q,k,v)
    const float* Wqkv = (const float*)d_in[3];
    const float* Wg   = (const float*)d_in[4];
    const float* bg   = (const float*)d_in[5];
    const float* Wo   = (const float*)d_in[6];
    const float* bo   = (const float*)d_in[7];
    const float* beta = (const float*)d_in[8];
    float* out = (float*)d_out;

    float *p_gate = nullptr, *p_Z = nullptr;
    cudaGetSymbolAddress((void**)&p_gate, g_gate);
    cudaGetSymbolAddress((void**)&p_Z,    g_Z);
    cudaFuncSetAttribute(k_pass2, cudaFuncAttributeMaxDynamicSharedMemorySize, SM2_BYTES);

    k_decay<<<1, NH_>>>();
    k_proj<<<dim3(SEQ_/64, B_*NH_), 256>>>(q, Wqkv);
    k_gemm1024<0><<<dim3(DIM_/128, B_*SEQ_/128), 256>>>(q, Wg, bg, p_gate);
    k_scan<<<B_*NH_, HD_>>>();
    k_coef<<<(B_*NH_*SEQ_)/8, 256>>>();
    k_pass2<<<dim3(SEQ_/128, B_*NH_), 256, SM2_BYTES>>>();
    k_gn<<<B_*SEQ_, 256>>>(beta);
    k_gemm1024<1><<<dim3(DIM_/128, B_*SEQ_/128), 256>>>(p_Z, Wo, bo, out);
}

// round 2
// speedup vs baseline: 1.3218x; 1.3218x over previous
#include <cuda_runtime.h>
#include <cuda_bf16.h>
#include <math.h>

// Problem constants
#define B_    4
#define SEQ_  2048
#define DIM_  1024
#define HD_   128
#define NH_   8
#define NC_   16          // chunks
#define CK_   128         // chunk size
#define SCALE_ 0.088388347648318447f   // 1/sqrt(128)

// ---------------- scratch (static device globals; no allocation) -----------
__device__ float g_Qh[(size_t)B_*NH_*SEQ_*HD_];   // per-head projected Q=K=V
__device__ float g_gate[(size_t)B_*SEQ_*DIM_];    // swish(q@Wg+bg)
__device__ float g_ho[(size_t)B_*NH_*SEQ_*HD_];   // retention head outputs
__device__ float g_Z [(size_t)B_*SEQ_*DIM_];      // gate * groupnorm(x)
__device__ float g_gpow[NH_*(SEQ_+1)];            // gamma^d tables
__device__ float g_rD  [NH_*SEQ_];                // 1/sqrt(colsum(D))[t]
__device__ float g_coef[B_*NH_*SEQ_];             // rD[t]/max(|cs[t]|,1)
__device__ float g_L    [B_*NH_*NC_*HD_];         // per-chunk scan partials
__device__ float g_carry[B_*NH_*NC_*HD_];         // scan carry into each chunk
__device__ float g_M[(size_t)B_*NH_*NC_*HD_*HD_]; // per-chunk K'^T V
__device__ float g_S[(size_t)B_*NH_*NC_*HD_*HD_]; // state at chunk starts

// ---------------- decay tables ---------------------------------------------
__global__ void k_decay() {
    int h = threadIdx.x;
    if (h >= NH_) return;
    double gamma = 1.0 - exp2(-5.0 - (double)h);
    double p = 1.0;
    for (int d = 0; d <= SEQ_; d++) { g_gpow[h*(SEQ_+1)+d] = (float)p; p *= gamma; }
    double lg = log(gamma);
    double om = 1.0 - gamma;
    for (int t = 0; t < SEQ_; t++) {
        double denom = 1.0 - exp((double)(SEQ_-t)*lg);   // 1 - gamma^(S-t)
        g_rD[h*SEQ_+t] = (float)sqrt(om/denom);
    }
}

// ---------------- per-head projection: Qh = q_head @ W_qkv[h] ---------------
__global__ __launch_bounds__(256)
void k_proj(const float* __restrict__ q, const float* __restrict__ Wq) {
    int bh = blockIdx.y;
    int b = bh / NH_, h = bh % NH_;
    int s0 = blockIdx.x * 64;
    __shared__ float As[16][64];
    __shared__ float Bs[16][132];
    int tid = threadIdx.x;
    int tx = tid & 15, ty = tid >> 4;
    float acc[4][8];
    #pragma unroll
    for (int i=0;i<4;i++) for (int j=0;j<8;j++) acc[i][j]=0.f;

    const float* A  = q  + (size_t)b*SEQ_*DIM_ + h*HD_;
    const float* Bm = Wq + (size_t)h*HD_*HD_;

    for (int k0 = 0; k0 < HD_; k0 += 16) {
        {
            int row = tid >> 2, qd = (tid & 3) << 2;
            float4 v = *(const float4*)(A + (size_t)(s0+row)*DIM_ + k0 + qd);
            As[qd+0][row]=v.x; As[qd+1][row]=v.y; As[qd+2][row]=v.z; As[qd+3][row]=v.w;
        }
        #pragma unroll
        for (int i = 0; i < 2; i++) {
            int idx = tid + i*256;
            int k = idx >> 5, c4 = (idx & 31) << 2;
            float4 v = *(const float4*)(Bm + (size_t)(k0+k)*HD_ + c4);
            *(float4*)&Bs[k][c4] = v;
        }
        __syncthreads();
        #pragma unroll
        for (int kk = 0; kk < 16; kk++) {
            float a[4], bb[8];
            #pragma unroll
            for (int i=0;i<4;i++) a[i] = As[kk][ty*4+i];
            #pragma unroll
            for (int j=0;j<8;j++) bb[j] = Bs[kk][tx*8+j];
            #pragma unroll
            for (int i=0;i<4;i++)
                #pragma unroll
                for (int j=0;j<8;j++) acc[i][j] = fmaf(a[i], bb[j], acc[i][j]);
        }
        __syncthreads();
    }
    float* outp = g_Qh + ((size_t)bh*SEQ_ + s0)*HD_;
    #pragma unroll
    for (int i=0;i<4;i++)
        #pragma unroll
        for (int j=0;j<8;j+=4) {
            float4 v = make_float4(acc[i][j],acc[i][j+1],acc[i][j+2],acc[i][j+3]);
            *(float4*)(outp + (size_t)(ty*4+i)*HD_ + tx*8 + j) = v;
        }
}

// ---------------- generic 1024-K GEMM: C = epi(A@B + bias) ------------------
template<int MODE>
__global__ __launch_bounds__(256)
void k_gemm1024(const float* __restrict__ A, const float* __restrict__ Bm,
                const float* __restrict__ bias, float* __restrict__ C) {
    const int K = DIM_, N = DIM_;
    int n0 = blockIdx.x * 128, m0 = blockIdx.y * 128;
    __shared__ float As[8][128];
    __shared__ float Bs[8][132];
    int tid = threadIdx.x;
    int tx = tid & 15, ty = tid >> 4;
    float acc[8][8];
    #pragma unroll
    for (int i=0;i<8;i++) for (int j=0;j<8;j++) acc[i][j]=0.f;

    for (int k0 = 0; k0 < K; k0 += 8) {
        {
            int row = tid >> 1, qq = (tid & 1) << 2;
            float4 v = *(const float4*)(A + (size_t)(m0+row)*K + k0 + qq);
            As[qq+0][row]=v.x; As[qq+1][row]=v.y; As[qq+2][row]=v.z; As[qq+3][row]=v.w;
        }
        {
            int k = tid >> 5, c4 = (tid & 31) << 2;
            float4 v = *(const float4*)(Bm + (size_t)(k0+k)*N + n0 + c4);
            *(float4*)&Bs[k][c4] = v;
        }
        __syncthreads();
        #pragma unroll
        for (int kk = 0; kk < 8; kk++) {
            float a[8], bb[8];
            #pragma unroll
            for (int i=0;i<8;i++) a[i] = As[kk][ty*8+i];
            #pragma unroll
            for (int j=0;j<8;j++) bb[j] = Bs[kk][tx*8+j];
            #pragma unroll
            for (int i=0;i<8;i++)
                #pragma unroll
                for (int j=0;j<8;j++) acc[i][j] = fmaf(a[i], bb[j], acc[i][j]);
        }
        __syncthreads();
    }
    #pragma unroll
    for (int i=0;i<8;i++) {
        int row = m0 + ty*8 + i;
        #pragma unroll
        for (int j=0;j<8;j+=4) {
            int col = n0 + tx*8 + j;
            float4 bsv = *(const float4*)(bias + col);
            float4 v;
            v.x = acc[i][j+0] + bsv.x;
            v.y = acc[i][j+1] + bsv.y;
            v.z = acc[i][j+2] + bsv.z;
            v.w = acc[i][j+3] + bsv.w;
            if (MODE == 0) {
                v.x = v.x / (1.f + __expf(-v.x));
                v.y = v.y / (1.f + __expf(-v.y));
                v.z = v.z / (1.f + __expf(-v.z));
                v.w = v.w / (1.f + __expf(-v.w));
            }
            *(float4*)(C + (size_t)row*N + col) = v;
        }
    }
}

// ---------------- blocked scan phase A: per-chunk weighted sums -------------
// L_c[d] = sum_{i=0..127} gamma^i * Q[c*128+i, d]
__global__ __launch_bounds__(128)
void k_chunkL() {
    int c = blockIdx.x, bh = blockIdx.y;
    int h = bh % NH_;
    int d = threadIdx.x;
    const float* Qc = g_Qh + ((size_t)bh*SEQ_ + c*CK_)*HD_;
    const float* gp = g_gpow + h*(SEQ_+1);
    float acc = 0.f;
    #pragma unroll 8
    for (int i = 0; i < CK_; i++)
        acc = fmaf(gp[i], Qc[(size_t)i*HD_ + d], acc);
    g_L[(bh*NC_ + c)*HD_ + d] = acc;
}

// ---------------- blocked scan phase B: cross-chunk carries -----------------
// U_c = L_c + gamma^128 * U_{c+1};  carry into chunk c = U_{c+1}
__global__ void k_carry() {
    int bh = blockIdx.x;
    int h = bh % NH_;
    int d = threadIdx.x;
    float g128 = g_gpow[h*(SEQ_+1) + CK_];
    float U = 0.f;
    for (int c = NC_-1; c >= 0; c--) {
        g_carry[(bh*NC_ + c)*HD_ + d] = U;
        U = fmaf(g128, U, g_L[(bh*NC_ + c)*HD_ + d]);
    }
}

// ---------------- blocked scan phase C: within-chunk scan + coef ------------
// u[t] = Q[t] + gamma*u[t+1];  cs[t] = scale*(Q[t].u[t])*rD[t]
__global__ __launch_bounds__(128)
void k_coef2() {
    int c = blockIdx.x, bh = blockIdx.y;
    int h = bh % NH_;
    int d = threadIdx.x;
    int lane = d & 31;
    float gamma = 1.f - exp2f(-5.f - (float)h);
    float u = g_carry[(bh*NC_ + c)*HD_ + d];
    const float* Qc = g_Qh + ((size_t)bh*SEQ_ + c*CK_)*HD_;
    const float* rdp = g_rD + h*SEQ_ + c*CK_;
    float* cfp = g_coef + bh*SEQ_ + c*CK_;
    __shared__ float red[4];
    for (int r = CK_-1; r >= 0; r--) {
        float qv = Qc[(size_t)r*HD_ + d];
        u = fmaf(gamma, u, qv);
        float p = qv * u;
        #pragma unroll
        for (int o = 16; o; o >>= 1) p += __shfl_xor_sync(0xffffffffu, p, o);
        if (lane == 0) red[d >> 5] = p;
        __syncthreads();
        if (d == 0) {
            float dot = red[0] + red[1] + red[2] + red[3];
            float rd = rdp[r];
            float cs = rd * (dot * SCALE_);
            cfp[r] = rd / fmaxf(fabsf(cs), 1.f);
        }
        __syncthreads();
    }
}

// ---------------- per-chunk M_c = Kd^T @ A ----------------------------------
// M_c[d,e] = sum_r gamma^(128-r) * w[t] * Q[t,d] * Q[t,e],  w=scale*coef
__global__ __launch_bounds__(256)
void k_chunkM() {
    int c = blockIdx.x, bh = blockIdx.y;
    int h = bh % NH_;
    int t0 = c * CK_;
    __shared__ float Qs[16][132];
    __shared__ float wk[16];
    int tid = threadIdx.x;
    int tx = tid & 15, ty = tid >> 4;
    float acc[8][8];
    #pragma unroll
    for (int i=0;i<8;i++) for (int j=0;j<8;j++) acc[i][j]=0.f;

    const float* Qb = g_Qh + (size_t)bh*SEQ_*HD_;
    const float* gp = g_gpow + h*(SEQ_+1);
    const float* cf = g_coef + bh*SEQ_;

    for (int k0 = 0; k0 < CK_; k0 += 16) {
        #pragma unroll
        for (int i=0;i<2;i++) {
            int idx = tid + i*256;
            int k = idx >> 5, c4 = (idx & 31) << 2;
            float4 v = *(const float4*)(Qb + (size_t)(t0+k0+k)*HD_ + c4);
            *(float4*)&Qs[k][c4] = v;
        }
        if (tid < 16)
            wk[tid] = gp[CK_ - (k0+tid)] * SCALE_ * cf[t0 + k0 + tid];
        __syncthreads();
        #pragma unroll
        for (int kk = 0; kk < 16; kk++) {
            float w = wk[kk];
            float a[8], b[8];
            #pragma unroll
            for (int i=0;i<8;i++) a[i] = w * Qs[kk][ty*8+i];
            #pragma unroll
            for (int j=0;j<8;j++) b[j] = Qs[kk][tx*8+j];
            #pragma unroll
            for (int i=0;i<8;i++)
                #pragma unroll
                for (int j=0;j<8;j++) acc[i][j] = fmaf(a[i], b[j], acc[i][j]);
        }
        __syncthreads();
    }
    float* Mp = g_M + ((size_t)(bh*NC_ + c)*HD_ + ty*8)*HD_ + tx*8;
    #pragma unroll
    for (int i=0;i<8;i++)
        #pragma unroll
        for (int j=0;j<8;j+=4) {
            float4 v = make_float4(acc[i][j],acc[i][j+1],acc[i][j+2],acc[i][j+3]);
            *(float4*)(Mp + (size_t)i*HD_ + j) = v;
        }
}

// ---------------- state combine: S_0=0; S_{c+1} = g128*S_c + M_c ------------
__global__ __launch_bounds__(256)
void k_state() {
    int bh = blockIdx.x;
    int h = bh % NH_;
    float g128 = g_gpow[h*(SEQ_+1) + CK_];
    int tid = threadIdx.x;
    float4 S[16];
    #pragma unroll
    for (int i=0;i<16;i++) S[i] = make_float4(0.f,0.f,0.f,0.f);
    for (int c = 0; c < NC_; c++) {
        float4* dst = (float4*)(g_S + (size_t)(bh*NC_ + c)*HD_*HD_);
        const float4* m = (const float4*)(g_M + (size_t)(bh*NC_ + c)*HD_*HD_);
        #pragma unroll
        for (int i=0;i<16;i++) dst[tid + i*256] = S[i];
        #pragma unroll
        for (int i=0;i<16;i++) {
            float4 mv = m[tid + i*256];
            S[i].x = fmaf(g128, S[i].x, mv.x);
            S[i].y = fmaf(g128, S[i].y, mv.y);
            S[i].z = fmaf(g128, S[i].z, mv.z);
            S[i].w = fmaf(g128, S[i].w, mv.w);
        }
    }
}

// ---------------- chunkwise output pass -------------------------------------
// O = masked-decayed(Q@Q^T) @ Q  +  diag(gamma^r) * (Q @ S_c)
#define SM2_BYTES ((128*132 + 2*16*132) * 4)
__global__ __launch_bounds__(256)
void k_pass2ck() {
    extern __shared__ float sm[];
    float* Ps = sm;                 // [128][132]
    float* As = sm + 128*132;       // [16][132]
    float* Bs = As + 16*132;        // [16][132]
    const int tid = threadIdx.x;
    const int tx = tid & 15, ty = tid >> 4;
    const int c  = blockIdx.x;
    const int bh = blockIdx.y;
    const int s0 = c * CK_;
    const int h  = bh % NH_;
    const float* Qb = g_Qh  + (size_t)bh * SEQ_ * HD_;
    const float* gp = g_gpow + h * (SEQ_+1);
    const float* cf = g_coef + bh * SEQ_;
    const float* Sc = g_S + (size_t)(bh*NC_ + c)*HD_*HD_;

    float rowf[8], cinv[8];
    #pragma unroll
    for (int i=0;i<8;i++) rowf[i] = gp[ty*8+i];
    #pragma unroll
    for (int j=0;j<8;j++) cinv[j] = 1.f / gp[tx*8+j];

    // ---- stage a: S = Q_c @ Q_c^T (single tile, A == B) ----
    {
        float S[8][8];
        #pragma unroll
        for (int i=0;i<8;i++) for (int j=0;j<8;j++) S[i][j]=0.f;
        for (int k0 = 0; k0 < HD_; k0 += 16) {
            #pragma unroll
            for (int i=0;i<2;i++) {
                int idx = tid + i*256;
                int row = idx >> 2;
                int qq  = (idx & 3) << 2;
                float4 va = *(const float4*)(Qb + (size_t)(s0+row)*HD_ + k0 + qq);
                As[(qq+0)*132+row]=va.x; As[(qq+1)*132+row]=va.y;
                As[(qq+2)*132+row]=va.z; As[(qq+3)*132+row]=va.w;
            }
            __syncthreads();
            #pragma unroll
            for (int kk=0; kk<16; kk++) {
                float a[8], b[8];
                #pragma unroll
                for (int i=0;i<8;i++) a[i] = As[kk*132 + ty*8 + i];
                #pragma unroll
                for (int j=0;j<8;j++) b[j] = As[kk*132 + tx*8 + j];
                #pragma unroll
                for (int i=0;i<8;i++)
                    #pragma unroll
                    for (int j=0;j<8;j++) S[i][j] = fmaf(a[i], b[j], S[i][j]);
            }
            __syncthreads();
        }
        // ---- stage b: mask + decay + coef, write P ----
        #pragma unroll
        for (int i=0;i<8;i++) {
            int s = ty*8 + i;
            float rf = SCALE_ * rowf[i];
            #pragma unroll
            for (int j=0;j<8;j++) {
                int t = tx*8 + j;
                float w = (s >= t) ? (rf * cinv[j] * cf[s0 + t]) : 0.f;
                Ps[s*132 + t] = S[i][j] * w;
            }
        }
        __syncthreads();
    }

    float O[8][8];
    #pragma unroll
    for (int i=0;i<8;i++) for (int j=0;j<8;j++) O[i][j]=0.f;

    // ---- stage c: O = P @ Q_c (intra-chunk) ----
    for (int k0 = 0; k0 < CK_; k0 += 16) {
        #pragma unroll
        for (int i=0;i<2;i++) {
            int idx = tid + i*256;
            int k  = idx >> 5;
            int c4 = (idx & 31) << 2;
            float4 v = *(const float4*)(Qb + (size_t)(s0+k0+k)*HD_ + c4);
            *(float4*)&Bs[k*132 + c4] = v;
        }
        __syncthreads();
        #pragma unroll
        for (int kk=0; kk<16; kk++) {
            float p[8], v[8];
            #pragma unroll
            for (int i=0;i<8;i++) p[i] = Ps[(ty*8+i)*132 + k0 + kk];
            #pragma unroll
            for (int j=0;j<8;j++) v[j] = Bs[kk*132 + tx*8 + j];
            #pragma unroll
            for (int i=0;i<8;i++)
                #pragma unroll
                for (int j=0;j<8;j++) O[i][j] = fmaf(p[i], v[j], O[i][j]);
        }
        __syncthreads();
    }

    // ---- stage d: O += diag(gamma^r) * (Q_c @ S_c) (inter-chunk) ----
    for (int k0 = 0; k0 < HD_; k0 += 16) {
        #pragma unroll
        for (int i=0;i<2;i++) {
            int idx = tid + i*256;
            int row = idx >> 2;
            int qq  = (idx & 3) << 2;
            float4 va = *(const float4*)(Qb + (size_t)(s0+row)*HD_ + k0 + qq);
            As[(qq+0)*132+row]=va.x; As[(qq+1)*132+row]=va.y;
            As[(qq+2)*132+row]=va.z; As[(qq+3)*132+row]=va.w;
        }
        #pragma unroll
        for (int i=0;i<2;i++) {
            int idx = tid + i*256;
            int k  = idx >> 5;
            int c4 = (idx & 31) << 2;
            float4 v = *(const float4*)(Sc + (size_t)(k0+k)*HD_ + c4);
            *(float4*)&Bs[k*132 + c4] = v;
        }
        __syncthreads();
        #pragma unroll
        for (int kk=0; kk<16; kk++) {
            float a[8], b[8];
            #pragma unroll
            for (int i=0;i<8;i++) a[i] = rowf[i] * As[kk*132 + ty*8 + i];
            #pragma unroll
            for (int j=0;j<8;j++) b[j] = Bs[kk*132 + tx*8 + j];
            #pragma unroll
            for (int i=0;i<8;i++)
                #pragma unroll
                for (int j=0;j<8;j++) O[i][j] = fmaf(a[i], b[j], O[i][j]);
        }
        __syncthreads();
    }

    float* outp = g_ho + ((size_t)bh*SEQ_ + s0) * HD_;
    #pragma unroll
    for (int i=0;i<8;i++)
        #pragma unroll
        for (int j=0;j<8;j+=4) {
            float4 v = make_float4(O[i][j],O[i][j+1],O[i][j+2],O[i][j+3]);
            *(float4*)(outp + (size_t)(ty*8+i)*HD_ + tx*8 + j) = v;
        }
}

// ---------------- GroupNorm(32 groups) + beta, then gate --------------------
__global__ __launch_bounds__(256)
void k_gn(const float* __restrict__ beta) {
    int row = blockIdx.x;
    int b = row >> 11, s = row & (SEQ_-1);
    int tid = threadIdx.x;
    int c = tid << 2;
    int h = c >> 7, d = c & 127;
    float4 x = *(const float4*)(g_ho + (((size_t)(b*NH_+h)*SEQ_ + s)*HD_ + d));

    float sum = x.x + x.y + x.z + x.w;
    #pragma unroll
    for (int o = 1; o < 8; o <<= 1) sum += __shfl_xor_sync(0xffffffffu, sum, o);
    float mu = sum * (1.f/32.f);

    float dx0 = x.x-mu, dx1 = x.y-mu, dx2 = x.z-mu, dx3 = x.w-mu;
    float sq = dx0*dx0 + dx1*dx1 + dx2*dx2 + dx3*dx3;
    #pragma unroll
    for (int o = 1; o < 8; o <<= 1) sq += __shfl_xor_sync(0xffffffffu, sq, o);
    float inv = rsqrtf(sq * (1.f/32.f) + 1e-3f);

    float4 be = *(const float4*)(beta + c);
    float4 g  = *(const float4*)(g_gate + (size_t)row*DIM_ + c);
    float4 z;
    z.x = (dx0*inv + be.x) * g.x;
    z.y = (dx1*inv + be.y) * g.y;
    z.z = (dx2*inv + be.z) * g.z;
    z.w = (dx3*inv + be.w) * g.w;
    *(float4*)(g_Z + (size_t)row*DIM_ + c) = z;
}

// ---------------- launch ----------------------------------------------------
extern "C" void kernel_launch(void* const* d_in, const int* in_sizes, int n_in,
                              void* d_out, int out_size) {
    (void)in_sizes; (void)n_in; (void)out_size;
    const float* q    = (const float*)d_in[0];
    const float* Wqkv = (const float*)d_in[3];
    const float* Wg   = (const float*)d_in[4];
    const float* bg   = (const float*)d_in[5];
    const float* Wo   = (const float*)d_in[6];
    const float* bo   = (const float*)d_in[7];
    const float* beta = (const float*)d_in[8];
    float* out = (float*)d_out;

    float *p_gate = nullptr, *p_Z = nullptr;
    cudaGetSymbolAddress((void**)&p_gate, g_gate);
    cudaGetSymbolAddress((void**)&p_Z,    g_Z);
    cudaFuncSetAttribute(k_pass2ck, cudaFuncAttributeMaxDynamicSharedMemorySize, SM2_BYTES);

    k_decay<<<1, NH_>>>();
    k_proj<<<dim3(SEQ_/64, B_*NH_), 256>>>(q, Wqkv);
    k_gemm1024<0><<<dim3(DIM_/128, B_*SEQ_/128), 256>>>(q, Wg, bg, p_gate);
    k_chunkL<<<dim3(NC_, B_*NH_), HD_>>>();
    k_carry<<<B_*NH_, HD_>>>();
    k_coef2<<<dim3(NC_, B_*NH_), HD_>>>();
    k_chunkM<<<dim3(NC_, B_*NH_), 256>>>();
    k_state<<<B_*NH_, 256>>>();
    k_pass2ck<<<dim3(NC_, B_*NH_), 256, SM2_BYTES>>>();
    k_gn<<<B_*SEQ_, 256>>>(beta);
    k_gemm1024<1><<<dim3(DIM_/128, B_*SEQ_/128), 256>>>(p_Z, Wo, bo, out);
}

// round 5
// speedup vs baseline: 1.6516x; 1.2495x over previous
#include <cuda_runtime.h>
#include <cuda_bf16.h>
#include <stdint.h>
#include <math.h>

// Problem constants
#define B_    4
#define SEQ_  2048
#define DIM_  1024
#define HD_   128
#define NH_   8
#define NC_   16          // chunks
#define CK_   128         // chunk size
#define SCALE_ 0.088388347648318447f   // 1/sqrt(128)

// ---------------- scratch (static device globals; no allocation) -----------
__device__ float g_Qh[(size_t)B_*NH_*SEQ_*HD_];   // per-head projected Q=K=V
__device__ float g_gate[(size_t)B_*SEQ_*DIM_];    // swish(q@Wg+bg)
__device__ float g_ho[(size_t)B_*NH_*SEQ_*HD_];   // retention head outputs
__device__ float g_Z [(size_t)B_*SEQ_*DIM_];      // gate * groupnorm(x)
__device__ float g_gpow[NH_*(SEQ_+1)];            // gamma^d tables
__device__ float g_rD  [NH_*SEQ_];                // 1/sqrt(colsum(D))[t]
__device__ float g_coef[B_*NH_*SEQ_];             // rD[t]/max(|cs[t]|,1)
__device__ float g_L    [B_*NH_*NC_*HD_];         // per-chunk scan partials
__device__ float g_carry[B_*NH_*NC_*HD_];         // scan carry into each chunk
__device__ float g_M[(size_t)B_*NH_*NC_*HD_*HD_]; // per-chunk K'^T V
__device__ float g_S[(size_t)B_*NH_*NC_*HD_*HD_]; // state at chunk starts

// ---------------- tf32 helpers ----------------------------------------------
__device__ __forceinline__ uint32_t f2tf(float x) {
    uint32_t r;
    asm("cvt.rna.tf32.f32 %0, %1;" : "=r"(r) : "f"(x));
    return r;
}
__device__ __forceinline__ void mma_tf32(float* c, const uint32_t* a, const uint32_t* b) {
    asm volatile(
        "mma.sync.aligned.m16n8k8.row.col.f32.tf32.tf32.f32 "
        "{%0,%1,%2,%3}, {%4,%5,%6,%7}, {%8,%9}, {%0,%1,%2,%3};"
        : "+f"(c[0]), "+f"(c[1]), "+f"(c[2]), "+f"(c[3])
        : "r"(a[0]), "r"(a[1]), "r"(a[2]), "r"(a[3]), "r"(b[0]), "r"(b[1]));
}

// ---------------- decay tables ---------------------------------------------
__global__ void k_decay() {
    int h = threadIdx.x;
    if (h >= NH_) return;
    double gamma = 1.0 - exp2(-5.0 - (double)h);
    double p = 1.0;
    for (int d = 0; d <= SEQ_; d++) { g_gpow[h*(SEQ_+1)+d] = (float)p; p *= gamma; }
    double lg = log(gamma);
    double om = 1.0 - gamma;
    for (int t = 0; t < SEQ_; t++) {
        double denom = 1.0 - exp((double)(SEQ_-t)*lg);
        g_rD[h*SEQ_+t] = (float)sqrt(om/denom);
    }
}

// ---------------- per-head projection: Qh = q_head @ W_qkv[h] ---------------
__global__ __launch_bounds__(256)
void k_proj(const float* __restrict__ q, const float* __restrict__ Wq) {
    int bh = blockIdx.y;
    int b = bh / NH_, h = bh % NH_;
    int s0 = blockIdx.x * 64;
    __shared__ float As[16][64];
    __shared__ float Bs[16][132];
    int tid = threadIdx.x;
    int tx = tid & 15, ty = tid >> 4;
    float acc[4][8];
    #pragma unroll
    for (int i=0;i<4;i++) for (int j=0;j<8;j++) acc[i][j]=0.f;

    const float* A  = q  + (size_t)b*SEQ_*DIM_ + h*HD_;
    const float* Bm = Wq + (size_t)h*HD_*HD_;

    for (int k0 = 0; k0 < HD_; k0 += 16) {
        {
            int row = tid >> 2, qd = (tid & 3) << 2;
            float4 v = *(const float4*)(A + (size_t)(s0+row)*DIM_ + k0 + qd);
            As[qd+0][row]=v.x; As[qd+1][row]=v.y; As[qd+2][row]=v.z; As[qd+3][row]=v.w;
        }
        #pragma unroll
        for (int i = 0; i < 2; i++) {
            int idx = tid + i*256;
            int k = idx >> 5, c4 = (idx & 31) << 2;
            float4 v = *(const float4*)(Bm + (size_t)(k0+k)*HD_ + c4);
            *(float4*)&Bs[k][c4] = v;
        }
        __syncthreads();
        #pragma unroll
        for (int kk = 0; kk < 16; kk++) {
            float a[4], bb[8];
            #pragma unroll
            for (int i=0;i<4;i++) a[i] = As[kk][ty*4+i];
            #pragma unroll
            for (int j=0;j<8;j++) bb[j] = Bs[kk][tx*8+j];
            #pragma unroll
            for (int i=0;i<4;i++)
                #pragma unroll
                for (int j=0;j<8;j++) acc[i][j] = fmaf(a[i], bb[j], acc[i][j]);
        }
        __syncthreads();
    }
    float* outp = g_Qh + ((size_t)bh*SEQ_ + s0)*HD_;
    #pragma unroll
    for (int i=0;i<4;i++)
        #pragma unroll
        for (int j=0;j<8;j+=4) {
            float4 v = make_float4(acc[i][j],acc[i][j+1],acc[i][j+2],acc[i][j+3]);
            *(float4*)(outp + (size_t)(ty*4+i)*HD_ + tx*8 + j) = v;
        }
}

// ---------------- TF32 tensor-core 1024-K GEMM: C = epi(A@B + bias) ---------
// 128x128 block tile, 8 warps (2x4), each warp 64x32 via m16n8k8.
// MODE 0: swish epilogue; MODE 1: plain bias epilogue.
template<int MODE>
__global__ __launch_bounds__(256)
void k_gemm_tc(const float* __restrict__ A, const float* __restrict__ Bm,
               const float* __restrict__ bias, float* __restrict__ C) {
    const int K = DIM_, N = DIM_;
    const int n0 = blockIdx.x * 128, m0 = blockIdx.y * 128;
    __shared__ uint32_t As[128][36];   // [m][k] pad->conflict-free frag reads
    __shared__ uint32_t Bs[32][136];   // [k][n]
    const int tid  = threadIdx.x;
    const int lane = tid & 31, wid = tid >> 5;
    const int wm = (wid & 1) * 64, wn = (wid >> 1) * 32;
    const int gid = lane >> 2, tig = lane & 3;

    float c[4][4][4];
    #pragma unroll
    for (int mt=0;mt<4;mt++)
        #pragma unroll
        for (int nt=0;nt<4;nt++)
            #pragma unroll
            for (int r=0;r<4;r++) c[mt][nt][r] = 0.f;

    for (int k0 = 0; k0 < K; k0 += 32) {
        // A tile 128x32 -> As[m][k]
        #pragma unroll
        for (int i = 0; i < 4; i++) {
            int idx = tid + i*256;
            int row = idx >> 3, cg = (idx & 7) << 2;
            float4 v = *(const float4*)(A + (size_t)(m0+row)*K + k0 + cg);
            As[row][cg+0]=f2tf(v.x); As[row][cg+1]=f2tf(v.y);
            As[row][cg+2]=f2tf(v.z); As[row][cg+3]=f2tf(v.w);
        }
        // B tile 32x128 -> Bs[k][n]
        #pragma unroll
        for (int i = 0; i < 4; i++) {
            int idx = tid + i*256;
            int kr = idx >> 5, cg = (idx & 31) << 2;
            float4 v = *(const float4*)(Bm + (size_t)(k0+kr)*N + n0 + cg);
            Bs[kr][cg+0]=f2tf(v.x); Bs[kr][cg+1]=f2tf(v.y);
            Bs[kr][cg+2]=f2tf(v.z); Bs[kr][cg+3]=f2tf(v.w);
        }
        __syncthreads();
        #pragma unroll
        for (int k8 = 0; k8 < 4; k8++) {
            const int ko = k8 * 8;
            uint32_t a[4][4], b[4][2];
            #pragma unroll
            for (int mt=0;mt<4;mt++) {
                int mr = wm + mt*16 + gid;
                a[mt][0] = As[mr    ][ko+tig  ];
                a[mt][1] = As[mr + 8][ko+tig  ];
                a[mt][2] = As[mr    ][ko+tig+4];
                a[mt][3] = As[mr + 8][ko+tig+4];
            }
            #pragma unroll
            for (int nt=0;nt<4;nt++) {
                int nc = wn + nt*8 + gid;
                b[nt][0] = Bs[ko+tig  ][nc];
                b[nt][1] = Bs[ko+tig+4][nc];
            }
            #pragma unroll
            for (int mt=0;mt<4;mt++)
                #pragma unroll
                for (int nt=0;nt<4;nt++)
                    mma_tf32(c[mt][nt], a[mt], b[nt]);
        }
        __syncthreads();
    }

    // epilogue
    #pragma unroll
    for (int nt=0;nt<4;nt++) {
        int col = n0 + wn + nt*8 + tig*2;
        float bv0 = bias[col], bv1 = bias[col+1];
        #pragma unroll
        for (int mt=0;mt<4;mt++) {
            int row = m0 + wm + mt*16 + gid;
            #pragma unroll
            for (int half=0; half<2; half++) {
                int r = row + half*8;
                float v0 = c[mt][nt][half*2+0] + bv0;
                float v1 = c[mt][nt][half*2+1] + bv1;
                if (MODE == 0) {
                    v0 = v0 / (1.f + __expf(-v0));
                    v1 = v1 / (1.f + __expf(-v1));
                }
                float2 o = make_float2(v0, v1);
                *(float2*)(C + (size_t)r*N + col) = o;
            }
        }
    }
}

// ---------------- blocked scan phase A: per-chunk weighted sums -------------
__global__ __launch_bounds__(128)
void k_chunkL() {
    int c = blockIdx.x, bh = blockIdx.y;
    int h = bh % NH_;
    int d = threadIdx.x;
    const float* Qc = g_Qh + ((size_t)bh*SEQ_ + c*CK_)*HD_;
    const float* gp = g_gpow + h*(SEQ_+1);
    float acc = 0.f;
    #pragma unroll 8
    for (int i = 0; i < CK_; i++)
        acc = fmaf(gp[i], Qc[(size_t)i*HD_ + d], acc);
    g_L[(bh*NC_ + c)*HD_ + d] = acc;
}

// ---------------- blocked scan phase B: cross-chunk carries -----------------
__global__ void k_carry() {
    int bh = blockIdx.x;
    int h = bh % NH_;
    int d = threadIdx.x;
    float g128 = g_gpow[h*(SEQ_+1) + CK_];
    float U = 0.f;
    for (int c = NC_-1; c >= 0; c--) {
        g_carry[(bh*NC_ + c)*HD_ + d] = U;
        U = fmaf(g128, U, g_L[(bh*NC_ + c)*HD_ + d]);
    }
}

// ---------------- blocked scan phase C: warp-per-chunk scan + coef ----------
__global__ __launch_bounds__(128)
void k_coef2() {
    int wid = threadIdx.x >> 5, lane = threadIdx.x & 31;
    int c = blockIdx.x * 4 + wid, bh = blockIdx.y;
    int h = bh % NH_;
    float gamma = 1.f - exp2f(-5.f - (float)h);
    const float* Qc  = g_Qh + ((size_t)bh*SEQ_ + c*CK_)*HD_;
    const float* rdp = g_rD + h*SEQ_ + c*CK_;
    float* cfp = g_coef + bh*SEQ_ + c*CK_;
    float4 u = *(const float4*)(g_carry + (bh*NC_ + c)*HD_ + lane*4);
    for (int r = CK_-1; r >= 0; r--) {
        float4 qv = *(const float4*)(Qc + (size_t)r*HD_ + lane*4);
        u.x = fmaf(gamma, u.x, qv.x);
        u.y = fmaf(gamma, u.y, qv.y);
        u.z = fmaf(gamma, u.z, qv.z);
        u.w = fmaf(gamma, u.w, qv.w);
        float p = qv.x*u.x + qv.y*u.y + qv.z*u.z + qv.w*u.w;
        #pragma unroll
        for (int o = 16; o; o >>= 1) p += __shfl_xor_sync(0xffffffffu, p, o);
        if (lane == 0) {
            float rd = rdp[r];
            float cs = rd * (p * SCALE_);
            cfp[r] = rd / fmaxf(fabsf(cs), 1.f);
        }
    }
}

// ---------------- per-chunk M_c = Kd^T @ A ----------------------------------
__global__ __launch_bounds__(256)
void k_chunkM() {
    int c = blockIdx.x, bh = blockIdx.y;
    int h = bh % NH_;
    int t0 = c * CK_;
    __shared__ float Qs[16][132];
    __shared__ float wk[16];
    int tid = threadIdx.x;
    int tx = tid & 15, ty = tid >> 4;
    float acc[8][8];
    #pragma unroll
    for (int i=0;i<8;i++) for (int j=0;j<8;j++) acc[i][j]=0.f;

    const float* Qb = g_Qh + (size_t)bh*SEQ_*HD_;
    const float* gp = g_gpow + h*(SEQ_+1);
    const float* cf = g_coef + bh*SEQ_;

    for (int k0 = 0; k0 < CK_; k0 += 16) {
        #pragma unroll
        for (int i=0;i<2;i++) {
            int idx = tid + i*256;
            int k = idx >> 5, c4 = (idx & 31) << 2;
            float4 v = *(const float4*)(Qb + (size_t)(t0+k0+k)*HD_ + c4);
            *(float4*)&Qs[k][c4] = v;
        }
        if (tid < 16)
            wk[tid] = gp[CK_ - (k0+tid)] * SCALE_ * cf[t0 + k0 + tid];
        __syncthreads();
        #pragma unroll
        for (int kk = 0; kk < 16; kk++) {
            float w = wk[kk];
            float a[8], b[8];
            #pragma unroll
            for (int i=0;i<8;i++) a[i] = w * Qs[kk][ty*8+i];
            #pragma unroll
            for (int j=0;j<8;j++) b[j] = Qs[kk][tx*8+j];
            #pragma unroll
            for (int i=0;i<8;i++)
                #pragma unroll
                for (int j=0;j<8;j++) acc[i][j] = fmaf(a[i], b[j], acc[i][j]);
        }
        __syncthreads();
    }
    float* Mp = g_M + ((size_t)(bh*NC_ + c)*HD_ + ty*8)*HD_ + tx*8;
    #pragma unroll
    for (int i=0;i<8;i++)
        #pragma unroll
        for (int j=0;j<8;j+=4) {
            float4 v = make_float4(acc[i][j],acc[i][j+1],acc[i][j+2],acc[i][j+3]);
            *(float4*)(Mp + (size_t)i*HD_ + j) = v;
        }
}

// ---------------- state combine: S_0=0; S_{c+1} = g128*S_c + M_c ------------
__global__ __launch_bounds__(256)
void k_state() {
    int bh = blockIdx.x;
    int h = bh % NH_;
    float g128 = g_gpow[h*(SEQ_+1) + CK_];
    int tid = threadIdx.x;
    float4 S[16];
    #pragma unroll
    for (int i=0;i<16;i++) S[i] = make_float4(0.f,0.f,0.f,0.f);
    for (int c = 0; c < NC_; c++) {
        float4* dst = (float4*)(g_S + (size_t)(bh*NC_ + c)*HD_*HD_);
        const float4* m = (const float4*)(g_M + (size_t)(bh*NC_ + c)*HD_*HD_);
        #pragma unroll
        for (int i=0;i<16;i++) dst[tid + i*256] = S[i];
        #pragma unroll
        for (int i=0;i<16;i++) {
            float4 mv = m[tid + i*256];
            S[i].x = fmaf(g128, S[i].x, mv.x);
            S[i].y = fmaf(g128, S[i].y, mv.y);
            S[i].z = fmaf(g128, S[i].z, mv.z);
            S[i].w = fmaf(g128, S[i].w, mv.w);
        }
    }
}

// ---------------- chunkwise output pass -------------------------------------
#define SM2_BYTES ((128*132 + 2*16*132) * 4)
__global__ __launch_bounds__(256)
void k_pass2ck() {
    extern __shared__ float sm[];
    float* Ps = sm;
    float* As = sm + 128*132;
    float* Bs = As + 16*132;
    const int tid = threadIdx.x;
    const int tx = tid & 15, ty = tid >> 4;
    const int c  = blockIdx.x;
    const int bh = blockIdx.y;
    const int s0 = c * CK_;
    const int h  = bh % NH_;
    const float* Qb = g_Qh  + (size_t)bh * SEQ_ * HD_;
    const float* gp = g_gpow + h * (SEQ_+1);
    const float* cf = g_coef + bh * SEQ_;
    const float* Sc = g_S + (size_t)(bh*NC_ + c)*HD_*HD_;

    float rowf[8], cinv[8];
    #pragma unroll
    for (int i=0;i<8;i++) rowf[i] = gp[ty*8+i];
    #pragma unroll
    for (int j=0;j<8;j++) cinv[j] = 1.f / gp[tx*8+j];

    {
        float S[8][8];
        #pragma unroll
        for (int i=0;i<8;i++) for (int j=0;j<8;j++) S[i][j]=0.f;
        for (int k0 = 0; k0 < HD_; k0 += 16) {
            #pragma unroll
            for (int i=0;i<2;i++) {
                int idx = tid + i*256;
                int row = idx >> 2;
                int qq  = (idx & 3) << 2;
                float4 va = *(const float4*)(Qb + (size_t)(s0+row)*HD_ + k0 + qq);
                As[(qq+0)*132+row]=va.x; As[(qq+1)*132+row]=va.y;
                As[(qq+2)*132+row]=va.z; As[(qq+3)*132+row]=va.w;
            }
            __syncthreads();
            #pragma unroll
            for (int kk=0; kk<16; kk++) {
                float a[8], b[8];
                #pragma unroll
                for (int i=0;i<8;i++) a[i] = As[kk*132 + ty*8 + i];
                #pragma unroll
                for (int j=0;j<8;j++) b[j] = As[kk*132 + tx*8 + j];
                #pragma unroll
                for (int i=0;i<8;i++)
                    #pragma unroll
                    for (int j=0;j<8;j++) S[i][j] = fmaf(a[i], b[j], S[i][j]);
            }
            __syncthreads();
        }
        #pragma unroll
        for (int i=0;i<8;i++) {
            int s = ty*8 + i;
            float rf = SCALE_ * rowf[i];
            #pragma unroll
            for (int j=0;j<8;j++) {
                int t = tx*8 + j;
                float w = (s >= t) ? (rf * cinv[j] * cf[s0 + t]) : 0.f;
                Ps[s*132 + t] = S[i][j] * w;
            }
        }
        __syncthreads();
    }

    float O[8][8];
    #pragma unroll
    for (int i=0;i<8;i++) for (int j=0;j<8;j++) O[i][j]=0.f;

    for (int k0 = 0; k0 < CK_; k0 += 16) {
        #pragma unroll
        for (int i=0;i<2;i++) {
            int idx = tid + i*256;
            int k  = idx >> 5;
            int c4 = (idx & 31) << 2;
            float4 v = *(const float4*)(Qb + (size_t)(s0+k0+k)*HD_ + c4);
            *(float4*)&Bs[k*132 + c4] = v;
        }
        __syncthreads();
        #pragma unroll
        for (int kk=0; kk<16; kk++) {
            float p[8], v[8];
            #pragma unroll
            for (int i=0;i<8;i++) p[i] = Ps[(ty*8+i)*132 + k0 + kk];
            #pragma unroll
            for (int j=0;j<8;j++) v[j] = Bs[kk*132 + tx*8 + j];
            #pragma unroll
            for (int i=0;i<8;i++)
                #pragma unroll
                for (int j=0;j<8;j++) O[i][j] = fmaf(p[i], v[j], O[i][j]);
        }
        __syncthreads();
    }

    for (int k0 = 0; k0 < HD_; k0 += 16) {
        #pragma unroll
        for (int i=0;i<2;i++) {
            int idx = tid + i*256;
            int row = idx >> 2;
            int qq  = (idx & 3) << 2;
            float4 va = *(const float4*)(Qb + (size_t)(s0+row)*HD_ + k0 + qq);
            As[(qq+0)*132+row]=va.x; As[(qq+1)*132+row]=va.y;
            As[(qq+2)*132+row]=va.z; As[(qq+3)*132+row]=va.w;
        }
        #pragma unroll
        for (int i=0;i<2;i++) {
            int idx = tid + i*256;
            int k  = idx >> 5;
            int c4 = (idx & 31) << 2;
            float4 v = *(const float4*)(Sc + (size_t)(k0+k)*HD_ + c4);
            *(float4*)&Bs[k*132 + c4] = v;
        }
        __syncthreads();
        #pragma unroll
        for (int kk=0; kk<16; kk++) {
            float a[8], b[8];
            #pragma unroll
            for (int i=0;i<8;i++) a[i] = rowf[i] * As[kk*132 + ty*8 + i];
            #pragma unroll
            for (int j=0;j<8;j++) b[j] = Bs[kk*132 + tx*8 + j];
            #pragma unroll
            for (int i=0;i<8;i++)
                #pragma unroll
                for (int j=0;j<8;j++) O[i][j] = fmaf(a[i], b[j], O[i][j]);
        }
        __syncthreads();
    }

    float* outp = g_ho + ((size_t)bh*SEQ_ + s0) * HD_;
    #pragma unroll
    for (int i=0;i<8;i++)
        #pragma unroll
        for (int j=0;j<8;j+=4) {
            float4 v = make_float4(O[i][j],O[i][j+1],O[i][j+2],O[i][j+3]);
            *(float4*)(outp + (size_t)(ty*8+i)*HD_ + tx*8 + j) = v;
        }
}

// ---------------- GroupNorm(32 groups) + beta, then gate --------------------
__global__ __launch_bounds__(256)
void k_gn(const float* __restrict__ beta) {
    int row = blockIdx.x;
    int b = row >> 11, s = row & (SEQ_-1);
    int tid = threadIdx.x;
    int c = tid << 2;
    int h = c >> 7, d = c & 127;
    float4 x = *(const float4*)(g_ho + (((size_t)(b*NH_+h)*SEQ_ + s)*HD_ + d));

    float sum = x.x + x.y + x.z + x.w;
    #pragma unroll
    for (int o = 1; o < 8; o <<= 1) sum += __shfl_xor_sync(0xffffffffu, sum, o);
    float mu = sum * (1.f/32.f);

    float dx0 = x.x-mu, dx1 = x.y-mu, dx2 = x.z-mu, dx3 = x.w-mu;
    float sq = dx0*dx0 + dx1*dx1 + dx2*dx2 + dx3*dx3;
    #pragma unroll
    for (int o = 1; o < 8; o <<= 1) sq += __shfl_xor_sync(0xffffffffu, sq, o);
    float inv = rsqrtf(sq * (1.f/32.f) + 1e-3f);

    float4 be = *(const float4*)(beta + c);
    float4 g  = *(const float4*)(g_gate + (size_t)row*DIM_ + c);
    float4 z;
    z.x = (dx0*inv + be.x) * g.x;
    z.y = (dx1*inv + be.y) * g.y;
    z.z = (dx2*inv + be.z) * g.z;
    z.w = (dx3*inv + be.w) * g.w;
    *(float4*)(g_Z + (size_t)row*DIM_ + c) = z;
}

// ---------------- launch ----------------------------------------------------
extern "C" void kernel_launch(void* const* d_in, const int* in_sizes, int n_in,
                              void* d_out, int out_size) {
    (void)in_sizes; (void)n_in; (void)out_size;
    const float* q    = (const float*)d_in[0];
    const float* Wqkv = (const float*)d_in[3];
    const float* Wg   = (const float*)d_in[4];
    const float* bg   = (const float*)d_in[5];
    const float* Wo   = (const float*)d_in[6];
    const float* bo   = (const float*)d_in[7];
    const float* beta = (const float*)d_in[8];
    float* out = (float*)d_out;

    float *p_gate = nullptr, *p_Z = nullptr;
    cudaGetSymbolAddress((void**)&p_gate, g_gate);
    cudaGetSymbolAddress((void**)&p_Z,    g_Z);
    cudaFuncSetAttribute(k_pass2ck, cudaFuncAttributeMaxDynamicSharedMemorySize, SM2_BYTES);

    k_decay<<<1, NH_>>>();
    k_proj<<<dim3(SEQ_/64, B_*NH_), 256>>>(q, Wqkv);
    k_gemm_tc<0><<<dim3(DIM_/128, B_*SEQ_/128), 256>>>(q, Wg, bg, p_gate);
    k_chunkL<<<dim3(NC_, B_*NH_), HD_>>>();
    k_carry<<<B_*NH_, HD_>>>();
    k_coef2<<<dim3(NC_/4, B_*NH_), 128>>>();
    k_chunkM<<<dim3(NC_, B_*NH_), 256>>>();
    k_state<<<B_*NH_, 256>>>();
    k_pass2ck<<<dim3(NC_, B_*NH_), 256, SM2_BYTES>>>();
    k_gn<<<B_*SEQ_, 256>>>(beta);
    k_gemm_tc<1><<<dim3(DIM_/128, B_*SEQ_/128), 256>>>(p_Z, Wo, bo, out);
}

// round 6
// speedup vs baseline: 1.7096x; 1.0351x over previous
#include <cuda_runtime.h>
#include <cuda_bf16.h>
#include <stdint.h>
#include <math.h>

// Problem constants
#define B_    4
#define SEQ_  2048
#define DIM_  1024
#define HD_   128
#define NH_   8
#define NC_   16          // chunks
#define CK_   128         // chunk size
#define SCALE_ 0.088388347648318447f   // 1/sqrt(128)

// ---------------- scratch (static device globals; no allocation) -----------
__device__ float g_Qh[(size_t)B_*NH_*SEQ_*HD_];   // per-head projected Q=K=V
__device__ float g_gate[(size_t)B_*SEQ_*DIM_];    // swish(q@Wg+bg)
__device__ float g_ho[(size_t)B_*NH_*SEQ_*HD_];   // retention head outputs
__device__ float g_Z [(size_t)B_*SEQ_*DIM_];      // gate * groupnorm(x)
__device__ float g_gpow[NH_*(SEQ_+1)];            // gamma^d tables
__device__ float g_rD  [NH_*SEQ_];                // 1/sqrt(colsum(D))[t]
__device__ float g_coef[B_*NH_*SEQ_];             // rD[t]/max(|cs[t]|,1)
__device__ float g_L    [B_*NH_*NC_*HD_];         // per-chunk scan partials
__device__ float g_carry[B_*NH_*NC_*HD_];         // scan carry into each chunk
__device__ float g_M[(size_t)B_*NH_*NC_*HD_*HD_]; // per-chunk K'^T V
__device__ float g_S[(size_t)B_*NH_*NC_*HD_*HD_]; // state at chunk starts

// ---------------- tf32 helpers ----------------------------------------------
__device__ __forceinline__ uint32_t f2tf(float x) {
    uint32_t r;
    asm("cvt.rna.tf32.f32 %0, %1;" : "=r"(r) : "f"(x));
    return r;
}
__device__ __forceinline__ uint32_t f2tf_lo(float x, uint32_t hi) {
    return f2tf(x - __uint_as_float(hi));
}
__device__ __forceinline__ void mma_tf32(float* c, const uint32_t* a, const uint32_t* b) {
    asm volatile(
        "mma.sync.aligned.m16n8k8.row.col.f32.tf32.tf32.f32 "
        "{%0,%1,%2,%3}, {%4,%5,%6,%7}, {%8,%9}, {%0,%1,%2,%3};"
        : "+f"(c[0]), "+f"(c[1]), "+f"(c[2]), "+f"(c[3])
        : "r"(a[0]), "r"(a[1]), "r"(a[2]), "r"(a[3]), "r"(b[0]), "r"(b[1]));
}
// double-tf32: C += A*B with fp32-level accuracy (drop lo*lo)
__device__ __forceinline__ void mma_d2(float* c, const uint32_t* ah, const uint32_t* al,
                                       const uint32_t* bh, const uint32_t* bl) {
    mma_tf32(c, ah, bl);
    mma_tf32(c, al, bh);
    mma_tf32(c, ah, bh);
}

// ---------------- decay tables ---------------------------------------------
__global__ void k_decay() {
    int h = threadIdx.x;
    if (h >= NH_) return;
    double gamma = 1.0 - exp2(-5.0 - (double)h);
    double p = 1.0;
    for (int d = 0; d <= SEQ_; d++) { g_gpow[h*(SEQ_+1)+d] = (float)p; p *= gamma; }
    double lg = log(gamma);
    double om = 1.0 - gamma;
    for (int t = 0; t < SEQ_; t++) {
        double denom = 1.0 - exp((double)(SEQ_-t)*lg);
        g_rD[h*SEQ_+t] = (float)sqrt(om/denom);
    }
}

// ---------------- per-head projection: Qh = q_head @ W_qkv[h] ---------------
__global__ __launch_bounds__(256)
void k_proj(const float* __restrict__ q, const float* __restrict__ Wq) {
    int bh = blockIdx.y;
    int b = bh / NH_, h = bh % NH_;
    int s0 = blockIdx.x * 64;
    __shared__ float As[16][64];
    __shared__ float Bs[16][132];
    int tid = threadIdx.x;
    int tx = tid & 15, ty = tid >> 4;
    float acc[4][8];
    #pragma unroll
    for (int i=0;i<4;i++) for (int j=0;j<8;j++) acc[i][j]=0.f;

    const float* A  = q  + (size_t)b*SEQ_*DIM_ + h*HD_;
    const float* Bm = Wq + (size_t)h*HD_*HD_;

    for (int k0 = 0; k0 < HD_; k0 += 16) {
        {
            int row = tid >> 2, qd = (tid & 3) << 2;
            float4 v = *(const float4*)(A + (size_t)(s0+row)*DIM_ + k0 + qd);
            As[qd+0][row]=v.x; As[qd+1][row]=v.y; As[qd+2][row]=v.z; As[qd+3][row]=v.w;
        }
        #pragma unroll
        for (int i = 0; i < 2; i++) {
            int idx = tid + i*256;
            int k = idx >> 5, c4 = (idx & 31) << 2;
            float4 v = *(const float4*)(Bm + (size_t)(k0+k)*HD_ + c4);
            *(float4*)&Bs[k][c4] = v;
        }
        __syncthreads();
        #pragma unroll
        for (int kk = 0; kk < 16; kk++) {
            float a[4], bb[8];
            #pragma unroll
            for (int i=0;i<4;i++) a[i] = As[kk][ty*4+i];
            #pragma unroll
            for (int j=0;j<8;j++) bb[j] = Bs[kk][tx*8+j];
            #pragma unroll
            for (int i=0;i<4;i++)
                #pragma unroll
                for (int j=0;j<8;j++) acc[i][j] = fmaf(a[i], bb[j], acc[i][j]);
        }
        __syncthreads();
    }
    float* outp = g_Qh + ((size_t)bh*SEQ_ + s0)*HD_;
    #pragma unroll
    for (int i=0;i<4;i++)
        #pragma unroll
        for (int j=0;j<8;j+=4) {
            float4 v = make_float4(acc[i][j],acc[i][j+1],acc[i][j+2],acc[i][j+3]);
            *(float4*)(outp + (size_t)(ty*4+i)*HD_ + tx*8 + j) = v;
        }
}

// ---------------- TF32 tensor-core 1024-K GEMM: C = epi(A@B + bias) ---------
template<int MODE>
__global__ __launch_bounds__(256)
void k_gemm_tc(const float* __restrict__ A, const float* __restrict__ Bm,
               const float* __restrict__ bias, float* __restrict__ C) {
    const int K = DIM_, N = DIM_;
    const int n0 = blockIdx.x * 128, m0 = blockIdx.y * 128;
    __shared__ uint32_t As[128][36];
    __shared__ uint32_t Bs[32][136];
    const int tid  = threadIdx.x;
    const int lane = tid & 31, wid = tid >> 5;
    const int wm = (wid & 1) * 64, wn = (wid >> 1) * 32;
    const int gid = lane >> 2, tig = lane & 3;

    float c[4][4][4];
    #pragma unroll
    for (int mt=0;mt<4;mt++)
        #pragma unroll
        for (int nt=0;nt<4;nt++)
            #pragma unroll
            for (int r=0;r<4;r++) c[mt][nt][r] = 0.f;

    for (int k0 = 0; k0 < K; k0 += 32) {
        #pragma unroll
        for (int i = 0; i < 4; i++) {
            int idx = tid + i*256;
            int row = idx >> 3, cg = (idx & 7) << 2;
            float4 v = *(const float4*)(A + (size_t)(m0+row)*K + k0 + cg);
            As[row][cg+0]=f2tf(v.x); As[row][cg+1]=f2tf(v.y);
            As[row][cg+2]=f2tf(v.z); As[row][cg+3]=f2tf(v.w);
        }
        #pragma unroll
        for (int i = 0; i < 4; i++) {
            int idx = tid + i*256;
            int kr = idx >> 5, cg = (idx & 31) << 2;
            float4 v = *(const float4*)(Bm + (size_t)(k0+kr)*N + n0 + cg);
            Bs[kr][cg+0]=f2tf(v.x); Bs[kr][cg+1]=f2tf(v.y);
            Bs[kr][cg+2]=f2tf(v.z); Bs[kr][cg+3]=f2tf(v.w);
        }
        __syncthreads();
        #pragma unroll
        for (int k8 = 0; k8 < 4; k8++) {
            const int ko = k8 * 8;
            uint32_t a[4][4], b[4][2];
            #pragma unroll
            for (int mt=0;mt<4;mt++) {
                int mr = wm + mt*16 + gid;
                a[mt][0] = As[mr    ][ko+tig  ];
                a[mt][1] = As[mr + 8][ko+tig  ];
                a[mt][2] = As[mr    ][ko+tig+4];
                a[mt][3] = As[mr + 8][ko+tig+4];
            }
            #pragma unroll
            for (int nt=0;nt<4;nt++) {
                int nc = wn + nt*8 + gid;
                b[nt][0] = Bs[ko+tig  ][nc];
                b[nt][1] = Bs[ko+tig+4][nc];
            }
            #pragma unroll
            for (int mt=0;mt<4;mt++)
                #pragma unroll
                for (int nt=0;nt<4;nt++)
                    mma_tf32(c[mt][nt], a[mt], b[nt]);
        }
        __syncthreads();
    }

    #pragma unroll
    for (int nt=0;nt<4;nt++) {
        int col = n0 + wn + nt*8 + tig*2;
        float bv0 = bias[col], bv1 = bias[col+1];
        #pragma unroll
        for (int mt=0;mt<4;mt++) {
            int row = m0 + wm + mt*16 + gid;
            #pragma unroll
            for (int half=0; half<2; half++) {
                int r = row + half*8;
                float v0 = c[mt][nt][half*2+0] + bv0;
                float v1 = c[mt][nt][half*2+1] + bv1;
                if (MODE == 0) {
                    v0 = v0 / (1.f + __expf(-v0));
                    v1 = v1 / (1.f + __expf(-v1));
                }
                float2 o = make_float2(v0, v1);
                *(float2*)(C + (size_t)r*N + col) = o;
            }
        }
    }
}

// ---------------- blocked scan phase A: per-chunk weighted sums -------------
__global__ __launch_bounds__(128)
void k_chunkL() {
    int c = blockIdx.x, bh = blockIdx.y;
    int h = bh % NH_;
    int d = threadIdx.x;
    const float* Qc = g_Qh + ((size_t)bh*SEQ_ + c*CK_)*HD_;
    const float* gp = g_gpow + h*(SEQ_+1);
    float acc = 0.f;
    #pragma unroll 8
    for (int i = 0; i < CK_; i++)
        acc = fmaf(gp[i], Qc[(size_t)i*HD_ + d], acc);
    g_L[(bh*NC_ + c)*HD_ + d] = acc;
}

// ---------------- blocked scan phase B: cross-chunk carries -----------------
__global__ void k_carry() {
    int bh = blockIdx.x;
    int h = bh % NH_;
    int d = threadIdx.x;
    float g128 = g_gpow[h*(SEQ_+1) + CK_];
    float U = 0.f;
    for (int c = NC_-1; c >= 0; c--) {
        g_carry[(bh*NC_ + c)*HD_ + d] = U;
        U = fmaf(g128, U, g_L[(bh*NC_ + c)*HD_ + d]);
    }
}

// ---------------- blocked scan phase C: warp-per-chunk scan + coef ----------
__global__ __launch_bounds__(128)
void k_coef2() {
    int wid = threadIdx.x >> 5, lane = threadIdx.x & 31;
    int c = blockIdx.x * 4 + wid, bh = blockIdx.y;
    int h = bh % NH_;
    float gamma = 1.f - exp2f(-5.f - (float)h);
    const float* Qc  = g_Qh + ((size_t)bh*SEQ_ + c*CK_)*HD_;
    const float* rdp = g_rD + h*SEQ_ + c*CK_;
    float* cfp = g_coef + bh*SEQ_ + c*CK_;
    float4 u = *(const float4*)(g_carry + (bh*NC_ + c)*HD_ + lane*4);
    for (int r = CK_-1; r >= 0; r--) {
        float4 qv = *(const float4*)(Qc + (size_t)r*HD_ + lane*4);
        u.x = fmaf(gamma, u.x, qv.x);
        u.y = fmaf(gamma, u.y, qv.y);
        u.z = fmaf(gamma, u.z, qv.z);
        u.w = fmaf(gamma, u.w, qv.w);
        float p = qv.x*u.x + qv.y*u.y + qv.z*u.z + qv.w*u.w;
        #pragma unroll
        for (int o = 16; o; o >>= 1) p += __shfl_xor_sync(0xffffffffu, p, o);
        if (lane == 0) {
            float rd = rdp[r];
            float cs = rd * (p * SCALE_);
            cfp[r] = rd / fmaxf(fabsf(cs), 1.f);
        }
    }
}

// ---------------- per-chunk M_c = (w*Q)^T @ Q via double-TF32 mma ------------
#define CM_BYTES ((3*32*132)*4)
__global__ __launch_bounds__(256)
void k_chunkM() {
    extern __shared__ float smc[];
    float*    Qf = smc;                       // [32][132] fp32
    uint32_t* Bh = (uint32_t*)(smc + 32*132); // [32][132]
    uint32_t* Bl = Bh + 32*132;
    __shared__ float wk[32];

    const int c = blockIdx.x, bh = blockIdx.y;
    const int h = bh % NH_;
    const int t0 = c * CK_;
    const int tid = threadIdx.x;
    const int lane = tid & 31, wid = tid >> 5;
    const int gid = lane >> 2, tig = lane & 3;
    const int wm = (wid & 1) * 64, wn = (wid >> 1) * 32;

    const float* Qb = g_Qh + (size_t)bh*SEQ_*HD_;
    const float* gp = g_gpow + h*(SEQ_+1);
    const float* cf = g_coef + bh*SEQ_;

    float acc[4][4][4];
    #pragma unroll
    for (int mt=0;mt<4;mt++) for (int nt=0;nt<4;nt++) for (int r=0;r<4;r++) acc[mt][nt][r]=0.f;

    for (int k0 = 0; k0 < CK_; k0 += 32) {
        #pragma unroll
        for (int i = 0; i < 4; i++) {
            int idx = tid + i*256;
            int row = idx >> 5, c4 = (idx & 31) << 2;
            float4 v = *(const float4*)(Qb + (size_t)(t0+k0+row)*HD_ + c4);
            int base = row*132 + c4;
            Qf[base+0]=v.x; Qf[base+1]=v.y; Qf[base+2]=v.z; Qf[base+3]=v.w;
            uint32_t h0=f2tf(v.x), h1=f2tf(v.y), h2=f2tf(v.z), h3=f2tf(v.w);
            Bh[base+0]=h0; Bh[base+1]=h1; Bh[base+2]=h2; Bh[base+3]=h3;
            Bl[base+0]=f2tf_lo(v.x,h0); Bl[base+1]=f2tf_lo(v.y,h1);
            Bl[base+2]=f2tf_lo(v.z,h2); Bl[base+3]=f2tf_lo(v.w,h3);
        }
        if (tid < 32)
            wk[tid] = gp[CK_ - (k0+tid)] * SCALE_ * cf[t0 + k0 + tid];
        __syncthreads();
        #pragma unroll
        for (int k8 = 0; k8 < 4; k8++) {
            const int ko = k8*8;
            float w0 = wk[ko+tig], w1 = wk[ko+tig+4];
            uint32_t ah[4][4], al[4][4], bhf[4][2], blf[4][2];
            #pragma unroll
            for (int mt=0;mt<4;mt++) {
                int mr = wm + mt*16 + gid;
                float a0 = w0 * Qf[(ko+tig  )*132 + mr    ];
                float a1 = w0 * Qf[(ko+tig  )*132 + mr + 8];
                float a2 = w1 * Qf[(ko+tig+4)*132 + mr    ];
                float a3 = w1 * Qf[(ko+tig+4)*132 + mr + 8];
                ah[mt][0]=f2tf(a0); al[mt][0]=f2tf_lo(a0,ah[mt][0]);
                ah[mt][1]=f2tf(a1); al[mt][1]=f2tf_lo(a1,ah[mt][1]);
                ah[mt][2]=f2tf(a2); al[mt][2]=f2tf_lo(a2,ah[mt][2]);
                ah[mt][3]=f2tf(a3); al[mt][3]=f2tf_lo(a3,ah[mt][3]);
            }
            #pragma unroll
            for (int nt=0;nt<4;nt++) {
                int nc = wn + nt*8 + gid;
                bhf[nt][0] = Bh[(ko+tig)*132 + nc];
                bhf[nt][1] = Bh[(ko+tig+4)*132 + nc];
                blf[nt][0] = Bl[(ko+tig)*132 + nc];
                blf[nt][1] = Bl[(ko+tig+4)*132 + nc];
            }
            #pragma unroll
            for (int mt=0;mt<4;mt++)
                #pragma unroll
                for (int nt=0;nt<4;nt++)
                    mma_d2(acc[mt][nt], ah[mt], al[mt], bhf[nt], blf[nt]);
        }
        __syncthreads();
    }

    float* Mp = g_M + (size_t)(bh*NC_ + c)*HD_*HD_;
    #pragma unroll
    for (int nt=0;nt<4;nt++) {
        int col = wn + nt*8 + tig*2;
        #pragma unroll
        for (int mt=0;mt<4;mt++) {
            int row = wm + mt*16 + gid;
            *(float2*)(Mp + (size_t)row*HD_ + col)     = make_float2(acc[mt][nt][0], acc[mt][nt][1]);
            *(float2*)(Mp + (size_t)(row+8)*HD_ + col) = make_float2(acc[mt][nt][2], acc[mt][nt][3]);
        }
    }
}

// ---------------- state: S_c = sum_{j<c} g128^(c-1-j) * M_j (parallel) -------
__global__ __launch_bounds__(256)
void k_state() {
    int c = blockIdx.x, bh = blockIdx.y;
    int h = bh % NH_;
    float g128 = g_gpow[h*(SEQ_+1) + CK_];
    int tid = threadIdx.x;
    float4 acc[16];
    #pragma unroll
    for (int i=0;i<16;i++) acc[i] = make_float4(0.f,0.f,0.f,0.f);
    for (int j = 0; j < c; j++) {
        const float4* m = (const float4*)(g_M + (size_t)(bh*NC_ + j)*HD_*HD_);
        #pragma unroll
        for (int i=0;i<16;i++) {
            float4 mv = m[tid + i*256];
            acc[i].x = fmaf(g128, acc[i].x, mv.x);
            acc[i].y = fmaf(g128, acc[i].y, mv.y);
            acc[i].z = fmaf(g128, acc[i].z, mv.z);
            acc[i].w = fmaf(g128, acc[i].w, mv.w);
        }
    }
    float4* dst = (float4*)(g_S + (size_t)(bh*NC_ + c)*HD_*HD_);
    #pragma unroll
    for (int i=0;i<16;i++) dst[tid + i*256] = acc[i];
}

// ---------------- chunkwise output pass: double-TF32 tensor cores -----------
// O = masked-decayed(Q@Q^T)@Q + diag(gamma^r)*(Q@S_c)
#define SM2_BYTES ((3*128*132)*4)
__global__ __launch_bounds__(256, 1)
void k_pass2ck() {
    extern __shared__ float smf[];
    uint32_t* Qhi = (uint32_t*)smf;           // [128][132]
    uint32_t* Qlo = Qhi + 128*132;            // [128][132]
    float*    Ps  = smf + 2*128*132;          // [128][132] fp32 P; reused in stage d
    uint32_t* Shi = (uint32_t*)Ps;            // stage d: [32][132]
    uint32_t* Slo = Shi + 32*132;

    const int tid = threadIdx.x;
    const int lane = tid & 31, wid = tid >> 5;
    const int gid = lane >> 2, tig = lane & 3;
    const int wm = (wid & 1) * 64, wn = (wid >> 1) * 32;
    const int c = blockIdx.x, bh = blockIdx.y;
    const int s0 = c * CK_;
    const int h = bh % NH_;
    const float* Qb = g_Qh + ((size_t)bh*SEQ_ + s0)*HD_;
    const float* gp = g_gpow + h*(SEQ_+1);
    const float* cf = g_coef + bh*SEQ_ + s0;
    const float* Sc = g_S + (size_t)(bh*NC_ + c)*HD_*HD_;

    // load Q chunk -> hi/lo tiles
    #pragma unroll
    for (int i = 0; i < 16; i++) {
        int idx = tid + i*256;
        int row = idx >> 5, c4 = (idx & 31) << 2;
        float4 v = *(const float4*)(Qb + (size_t)row*HD_ + c4);
        int base = row*132 + c4;
        uint32_t h0=f2tf(v.x), h1=f2tf(v.y), h2=f2tf(v.z), h3=f2tf(v.w);
        Qhi[base+0]=h0; Qhi[base+1]=h1; Qhi[base+2]=h2; Qhi[base+3]=h3;
        Qlo[base+0]=f2tf_lo(v.x,h0); Qlo[base+1]=f2tf_lo(v.y,h1);
        Qlo[base+2]=f2tf_lo(v.z,h2); Qlo[base+3]=f2tf_lo(v.w,h3);
    }
    __syncthreads();

    // per-thread decay constants
    float rowg[8];        // gamma^row for rows wm+mt*16+gid(+8)
    #pragma unroll
    for (int mt=0;mt<4;mt++) {
        rowg[mt*2+0] = gp[wm + mt*16 + gid];
        rowg[mt*2+1] = gp[wm + mt*16 + gid + 8];
    }
    float colinv[8], cfv[8];
    #pragma unroll
    for (int nt=0;nt<4;nt++) {
        int col0 = wn + nt*8 + tig*2;
        colinv[nt*2+0] = 1.f / gp[col0];
        colinv[nt*2+1] = 1.f / gp[col0+1];
        cfv[nt*2+0] = cf[col0];
        cfv[nt*2+1] = cf[col0+1];
    }

    // ---- stage a: S = Q@Q^T ----
    float Sf[4][4][4];
    #pragma unroll
    for (int mt=0;mt<4;mt++) for (int nt=0;nt<4;nt++) for (int r=0;r<4;r++) Sf[mt][nt][r]=0.f;
    #pragma unroll 4
    for (int k8 = 0; k8 < 16; k8++) {
        const int ko = k8*8;
        uint32_t ah[4][4], al[4][4], bhf[4][2], blf[4][2];
        #pragma unroll
        for (int mt=0;mt<4;mt++) {
            int mr = wm + mt*16 + gid;
            ah[mt][0]=Qhi[mr*132+ko+tig];     al[mt][0]=Qlo[mr*132+ko+tig];
            ah[mt][1]=Qhi[(mr+8)*132+ko+tig]; al[mt][1]=Qlo[(mr+8)*132+ko+tig];
            ah[mt][2]=Qhi[mr*132+ko+tig+4];   al[mt][2]=Qlo[mr*132+ko+tig+4];
            ah[mt][3]=Qhi[(mr+8)*132+ko+tig+4];al[mt][3]=Qlo[(mr+8)*132+ko+tig+4];
        }
        #pragma unroll
        for (int nt=0;nt<4;nt++) {
            int nc = wn + nt*8 + gid;
            bhf[nt][0]=Qhi[nc*132+ko+tig];   blf[nt][0]=Qlo[nc*132+ko+tig];
            bhf[nt][1]=Qhi[nc*132+ko+tig+4]; blf[nt][1]=Qlo[nc*132+ko+tig+4];
        }
        #pragma unroll
        for (int mt=0;mt<4;mt++)
            #pragma unroll
            for (int nt=0;nt<4;nt++)
                mma_d2(Sf[mt][nt], ah[mt], al[mt], bhf[nt], blf[nt]);
    }

    // ---- stage b: apply mask/decay/coef, write P fp32 to smem ----
    #pragma unroll
    for (int mt=0;mt<4;mt++) {
        #pragma unroll
        for (int nt=0;nt<4;nt++) {
            #pragma unroll
            for (int r=0;r<4;r++) {
                int rw = wm + mt*16 + gid + (r>>1)*8;
                int cl = wn + nt*8 + tig*2 + (r&1);
                float w = (rw >= cl) ? (SCALE_ * rowg[mt*2+(r>>1)] * colinv[nt*2+(r&1)] * cfv[nt*2+(r&1)]) : 0.f;
                Ps[rw*132 + cl] = Sf[mt][nt][r] * w;
            }
        }
    }
    __syncthreads();

    // ---- stage c: O1 = P @ Q (on-the-fly split of P) ----
    float O1[4][4][4];
    #pragma unroll
    for (int mt=0;mt<4;mt++) for (int nt=0;nt<4;nt++) for (int r=0;r<4;r++) O1[mt][nt][r]=0.f;
    #pragma unroll 4
    for (int k8 = 0; k8 < 16; k8++) {
        const int ko = k8*8;
        uint32_t ah[4][4], al[4][4], bhf[4][2], blf[4][2];
        #pragma unroll
        for (int mt=0;mt<4;mt++) {
            int mr = wm + mt*16 + gid;
            float p0 = Ps[mr*132+ko+tig];
            float p1 = Ps[(mr+8)*132+ko+tig];
            float p2 = Ps[mr*132+ko+tig+4];
            float p3 = Ps[(mr+8)*132+ko+tig+4];
            ah[mt][0]=f2tf(p0); al[mt][0]=f2tf_lo(p0,ah[mt][0]);
            ah[mt][1]=f2tf(p1); al[mt][1]=f2tf_lo(p1,ah[mt][1]);
            ah[mt][2]=f2tf(p2); al[mt][2]=f2tf_lo(p2,ah[mt][2]);
            ah[mt][3]=f2tf(p3); al[mt][3]=f2tf_lo(p3,ah[mt][3]);
        }
        #pragma unroll
        for (int nt=0;nt<4;nt++) {
            int nc = wn + nt*8 + gid;
            bhf[nt][0]=Qhi[(ko+tig)*132+nc];   blf[nt][0]=Qlo[(ko+tig)*132+nc];
            bhf[nt][1]=Qhi[(ko+tig+4)*132+nc]; blf[nt][1]=Qlo[(ko+tig+4)*132+nc];
        }
        #pragma unroll
        for (int mt=0;mt<4;mt++)
            #pragma unroll
            for (int nt=0;nt<4;nt++)
                mma_d2(O1[mt][nt], ah[mt], al[mt], bhf[nt], blf[nt]);
    }
    __syncthreads();   // Ps reads done; safe to reuse region for S chunks

    // ---- stage d: O2 = Q @ S_c (k-chunked S staging into reused smem) ----
    float O2[4][4][4];
    #pragma unroll
    for (int mt=0;mt<4;mt++) for (int nt=0;nt<4;nt++) for (int r=0;r<4;r++) O2[mt][nt][r]=0.f;
    for (int k0 = 0; k0 < HD_; k0 += 32) {
        #pragma unroll
        for (int i = 0; i < 4; i++) {
            int idx = tid + i*256;
            int row = idx >> 5, c4 = (idx & 31) << 2;
            float4 v = *(const float4*)(Sc + (size_t)(k0+row)*HD_ + c4);
            int base = row*132 + c4;
            uint32_t h0=f2tf(v.x), h1=f2tf(v.y), h2=f2tf(v.z), h3=f2tf(v.w);
            Shi[base+0]=h0; Shi[base+1]=h1; Shi[base+2]=h2; Shi[base+3]=h3;
            Slo[base+0]=f2tf_lo(v.x,h0); Slo[base+1]=f2tf_lo(v.y,h1);
            Slo[base+2]=f2tf_lo(v.z,h2); Slo[base+3]=f2tf_lo(v.w,h3);
        }
        __syncthreads();
        #pragma unroll
        for (int k8 = 0; k8 < 4; k8++) {
            const int ko = k8*8;
            uint32_t ah[4][4], al[4][4], bhf[4][2], blf[4][2];
            #pragma unroll
            for (int mt=0;mt<4;mt++) {
                int mr = wm + mt*16 + gid;
                ah[mt][0]=Qhi[mr*132+k0+ko+tig];      al[mt][0]=Qlo[mr*132+k0+ko+tig];
                ah[mt][1]=Qhi[(mr+8)*132+k0+ko+tig];  al[mt][1]=Qlo[(mr+8)*132+k0+ko+tig];
                ah[mt][2]=Qhi[mr*132+k0+ko+tig+4];    al[mt][2]=Qlo[mr*132+k0+ko+tig+4];
                ah[mt][3]=Qhi[(mr+8)*132+k0+ko+tig+4];al[mt][3]=Qlo[(mr+8)*132+k0+ko+tig+4];
            }
            #pragma unroll
            for (int nt=0;nt<4;nt++) {
                int nc = wn + nt*8 + gid;
                bhf[nt][0]=Shi[(ko+tig)*132+nc];   blf[nt][0]=Slo[(ko+tig)*132+nc];
                bhf[nt][1]=Shi[(ko+tig+4)*132+nc]; blf[nt][1]=Slo[(ko+tig+4)*132+nc];
            }
            #pragma unroll
            for (int mt=0;mt<4;mt++)
                #pragma unroll
                for (int nt=0;nt<4;nt++)
                    mma_d2(O2[mt][nt], ah[mt], al[mt], bhf[nt], blf[nt]);
        }
        __syncthreads();
    }

    // ---- epilogue: out = O1 + gamma^row * O2 ----
    float* outp = g_ho + ((size_t)bh*SEQ_ + s0)*HD_;
    #pragma unroll
    for (int nt=0;nt<4;nt++) {
        int col = wn + nt*8 + tig*2;
        #pragma unroll
        for (int mt=0;mt<4;mt++) {
            int row = wm + mt*16 + gid;
            float g0 = rowg[mt*2+0], g1 = rowg[mt*2+1];
            float2 o0 = make_float2(O1[mt][nt][0] + g0*O2[mt][nt][0],
                                    O1[mt][nt][1] + g0*O2[mt][nt][1]);
            float2 o1 = make_float2(O1[mt][nt][2] + g1*O2[mt][nt][2],
                                    O1[mt][nt][3] + g1*O2[mt][nt][3]);
            *(float2*)(outp + (size_t)row*HD_ + col)     = o0;
            *(float2*)(outp + (size_t)(row+8)*HD_ + col) = o1;
        }
    }
}

// ---------------- GroupNorm(32 groups) + beta, then gate --------------------
__global__ __launch_bounds__(256)
void k_gn(const float* __restrict__ beta) {
    int row = blockIdx.x;
    int b = row >> 11, s = row & (SEQ_-1);
    int tid = threadIdx.x;
    int c = tid << 2;
    int h = c >> 7, d = c & 127;
    float4 x = *(const float4*)(g_ho + (((size_t)(b*NH_+h)*SEQ_ + s)*HD_ + d));

    float sum = x.x + x.y + x.z + x.w;
    #pragma unroll
    for (int o = 1; o < 8; o <<= 1) sum += __shfl_xor_sync(0xffffffffu, sum, o);
    float mu = sum * (1.f/32.f);

    float dx0 = x.x-mu, dx1 = x.y-mu, dx2 = x.z-mu, dx3 = x.w-mu;
    float sq = dx0*dx0 + dx1*dx1 + dx2*dx2 + dx3*dx3;
    #pragma unroll
    for (int o = 1; o < 8; o <<= 1) sq += __shfl_xor_sync(0xffffffffu, sq, o);
    float inv = rsqrtf(sq * (1.f/32.f) + 1e-3f);

    float4 be = *(const float4*)(beta + c);
    float4 g  = *(const float4*)(g_gate + (size_t)row*DIM_ + c);
    float4 z;
    z.x = (dx0*inv + be.x) * g.x;
    z.y = (dx1*inv + be.y) * g.y;
    z.z = (dx2*inv + be.z) * g.z;
    z.w = (dx3*inv + be.w) * g.w;
    *(float4*)(g_Z + (size_t)row*DIM_ + c) = z;
}

// ---------------- launch ----------------------------------------------------
extern "C" void kernel_launch(void* const* d_in, const int* in_sizes, int n_in,
                              void* d_out, int out_size) {
    (void)in_sizes; (void)n_in; (void)out_size;
    const float* q    = (const float*)d_in[0];
    const float* Wqkv = (const float*)d_in[3];
    const float* Wg   = (const float*)d_in[4];
    const float* bg   = (const float*)d_in[5];
    const float* Wo   = (const float*)d_in[6];
    const float* bo   = (const float*)d_in[7];
    const float* beta = (const float*)d_in[8];
    float* out = (float*)d_out;

    float *p_gate = nullptr, *p_Z = nullptr;
    cudaGetSymbolAddress((void**)&p_gate, g_gate);
    cudaGetSymbolAddress((void**)&p_Z,    g_Z);
    cudaFuncSetAttribute(k_pass2ck, cudaFuncAttributeMaxDynamicSharedMemorySize, SM2_BYTES);
    cudaFuncSetAttribute(k_chunkM,  cudaFuncAttributeMaxDynamicSharedMemorySize, CM_BYTES);

    k_decay<<<1, NH_>>>();
    k_proj<<<dim3(SEQ_/64, B_*NH_), 256>>>(q, Wqkv);
    k_gemm_tc<0><<<dim3(DIM_/128, B_*SEQ_/128), 256>>>(q, Wg, bg, p_gate);
    k_chunkL<<<dim3(NC_, B_*NH_), HD_>>>();
    k_carry<<<B_*NH_, HD_>>>();
    k_coef2<<<dim3(NC_/4, B_*NH_), 128>>>();
    k_chunkM<<<dim3(NC_, B_*NH_), 256, CM_BYTES>>>();
    k_state<<<dim3(NC_, B_*NH_), 256>>>();
    k_pass2ck<<<dim3(NC_, B_*NH_), 256, SM2_BYTES>>>();
    k_gn<<<B_*SEQ_, 256>>>(beta);
    k_gemm_tc<1><<<dim3(DIM_/128, B_*SEQ_/128), 256>>>(p_Z, Wo, bo, out);
}

// round 7
// speedup vs baseline: 8.2107x; 4.8028x over previous
#include <cuda_runtime.h>
#include <cuda_bf16.h>
#include <stdint.h>
#include <math.h>

// Problem constants
#define B_    4
#define SEQ_  2048
#define DIM_  1024
#define HD_   128
#define NH_   8
#define NC_   16          // chunks
#define CK_   128         // chunk size
#define SCALE_ 0.088388347648318447f   // 1/sqrt(128)

// ---------------- scratch (static device globals; no allocation) -----------
__device__ float g_Qh[(size_t)B_*NH_*SEQ_*HD_];   // per-head projected Q=K=V
__device__ float g_gate[(size_t)B_*SEQ_*DIM_];    // swish(q@Wg+bg)
__device__ float g_ho[(size_t)B_*NH_*SEQ_*HD_];   // retention head outputs
__device__ float g_Z [(size_t)B_*SEQ_*DIM_];      // gate * groupnorm(x)
__device__ float g_gpow[NH_*(SEQ_+1)];            // gamma^d tables
__device__ float g_rD  [NH_*SEQ_];                // 1/sqrt(colsum(D))[t]
__device__ float g_coef[B_*NH_*SEQ_];             // rD[t]/max(|cs[t]|,1)
__device__ float g_L    [B_*NH_*NC_*HD_];         // per-chunk scan partials
__device__ float g_carry[B_*NH_*NC_*HD_];         // scan carry into each chunk
__device__ float g_M[(size_t)B_*NH_*NC_*HD_*HD_]; // per-chunk K'^T V
__device__ float g_S[(size_t)B_*NH_*NC_*HD_*HD_]; // state at chunk starts

// ---------------- tf32 helpers ----------------------------------------------
__device__ __forceinline__ uint32_t f2tf(float x) {
    uint32_t r;
    asm("cvt.rna.tf32.f32 %0, %1;" : "=r"(r) : "f"(x));
    return r;
}
__device__ __forceinline__ uint32_t f2tf_lo(float x, uint32_t hi) {
    return f2tf(x - __uint_as_float(hi));
}
__device__ __forceinline__ void mma_tf32(float* c, const uint32_t* a, const uint32_t* b) {
    asm volatile(
        "mma.sync.aligned.m16n8k8.row.col.f32.tf32.tf32.f32 "
        "{%0,%1,%2,%3}, {%4,%5,%6,%7}, {%8,%9}, {%0,%1,%2,%3};"
        : "+f"(c[0]), "+f"(c[1]), "+f"(c[2]), "+f"(c[3])
        : "r"(a[0]), "r"(a[1]), "r"(a[2]), "r"(a[3]), "r"(b[0]), "r"(b[1]));
}
// double-tf32: C += A*B with fp32-level accuracy (drop lo*lo)
__device__ __forceinline__ void mma_d2(float* c, const uint32_t* ah, const uint32_t* al,
                                       const uint32_t* bh, const uint32_t* bl) {
    mma_tf32(c, ah, bl);
    mma_tf32(c, al, bh);
    mma_tf32(c, ah, bh);
}

// ---------------- decay tables (parallel closed-form) -----------------------
// gpow[d] = gamma^d = exp(d*ln(gamma));  rD[t] = sqrt((1-gamma)/(1-gamma^(S-t)))
__global__ void k_decay() {
    int h = blockIdx.x;
    double gamma = 1.0 - exp2(-5.0 - (double)h);
    double lg = log(gamma);
    double om = 1.0 - gamma;
    for (int d = threadIdx.x; d <= SEQ_; d += blockDim.x)
        g_gpow[h*(SEQ_+1)+d] = (float)exp((double)d * lg);
    for (int t = threadIdx.x; t < SEQ_; t += blockDim.x) {
        double denom = 1.0 - exp((double)(SEQ_-t)*lg);
        g_rD[h*SEQ_+t] = (float)sqrt(om/denom);
    }
}

// ---------------- per-head projection: Qh = q_head @ W_qkv[h] ---------------
__global__ __launch_bounds__(256)
void k_proj(const float* __restrict__ q, const float* __restrict__ Wq) {
    int bh = blockIdx.y;
    int b = bh / NH_, h = bh % NH_;
    int s0 = blockIdx.x * 64;
    __shared__ float As[16][64];
    __shared__ float Bs[16][132];
    int tid = threadIdx.x;
    int tx = tid & 15, ty = tid >> 4;
    float acc[4][8];
    #pragma unroll
    for (int i=0;i<4;i++) for (int j=0;j<8;j++) acc[i][j]=0.f;

    const float* A  = q  + (size_t)b*SEQ_*DIM_ + h*HD_;
    const float* Bm = Wq + (size_t)h*HD_*HD_;

    for (int k0 = 0; k0 < HD_; k0 += 16) {
        {
            int row = tid >> 2, qd = (tid & 3) << 2;
            float4 v = *(const float4*)(A + (size_t)(s0+row)*DIM_ + k0 + qd);
            As[qd+0][row]=v.x; As[qd+1][row]=v.y; As[qd+2][row]=v.z; As[qd+3][row]=v.w;
        }
        #pragma unroll
        for (int i = 0; i < 2; i++) {
            int idx = tid + i*256;
            int k = idx >> 5, c4 = (idx & 31) << 2;
            float4 v = *(const float4*)(Bm + (size_t)(k0+k)*HD_ + c4);
            *(float4*)&Bs[k][c4] = v;
        }
        __syncthreads();
        #pragma unroll
        for (int kk = 0; kk < 16; kk++) {
            float a[4], bb[8];
            #pragma unroll
            for (int i=0;i<4;i++) a[i] = As[kk][ty*4+i];
            #pragma unroll
            for (int j=0;j<8;j++) bb[j] = Bs[kk][tx*8+j];
            #pragma unroll
            for (int i=0;i<4;i++)
                #pragma unroll
                for (int j=0;j<8;j++) acc[i][j] = fmaf(a[i], bb[j], acc[i][j]);
        }
        __syncthreads();
    }
    float* outp = g_Qh + ((size_t)bh*SEQ_ + s0)*HD_;
    #pragma unroll
    for (int i=0;i<4;i++)
        #pragma unroll
        for (int j=0;j<8;j+=4) {
            float4 v = make_float4(acc[i][j],acc[i][j+1],acc[i][j+2],acc[i][j+3]);
            *(float4*)(outp + (size_t)(ty*4+i)*HD_ + tx*8 + j) = v;
        }
}

// ---------------- TF32 tensor-core 1024-K GEMM: C = epi(A@B + bias) ---------
template<int MODE>
__global__ __launch_bounds__(256)
void k_gemm_tc(const float* __restrict__ A, const float* __restrict__ Bm,
               const float* __restrict__ bias, float* __restrict__ C) {
    const int K = DIM_, N = DIM_;
    const int n0 = blockIdx.x * 128, m0 = blockIdx.y * 128;
    __shared__ uint32_t As[128][36];
    __shared__ uint32_t Bs[32][136];
    const int tid  = threadIdx.x;
    const int lane = tid & 31, wid = tid >> 5;
    const int wm = (wid & 1) * 64, wn = (wid >> 1) * 32;
    const int gid = lane >> 2, tig = lane & 3;

    float c[4][4][4];
    #pragma unroll
    for (int mt=0;mt<4;mt++)
        #pragma unroll
        for (int nt=0;nt<4;nt++)
            #pragma unroll
            for (int r=0;r<4;r++) c[mt][nt][r] = 0.f;

    for (int k0 = 0; k0 < K; k0 += 32) {
        #pragma unroll
        for (int i = 0; i < 4; i++) {
            int idx = tid + i*256;
            int row = idx >> 3, cg = (idx & 7) << 2;
            float4 v = *(const float4*)(A + (size_t)(m0+row)*K + k0 + cg);
            As[row][cg+0]=f2tf(v.x); As[row][cg+1]=f2tf(v.y);
            As[row][cg+2]=f2tf(v.z); As[row][cg+3]=f2tf(v.w);
        }
        #pragma unroll
        for (int i = 0; i < 4; i++) {
            int idx = tid + i*256;
            int kr = idx >> 5, cg = (idx & 31) << 2;
            float4 v = *(const float4*)(Bm + (size_t)(k0+kr)*N + n0 + cg);
            Bs[kr][cg+0]=f2tf(v.x); Bs[kr][cg+1]=f2tf(v.y);
            Bs[kr][cg+2]=f2tf(v.z); Bs[kr][cg+3]=f2tf(v.w);
        }
        __syncthreads();
        #pragma unroll
        for (int k8 = 0; k8 < 4; k8++) {
            const int ko = k8 * 8;
            uint32_t a[4][4], b[4][2];
            #pragma unroll
            for (int mt=0;mt<4;mt++) {
                int mr = wm + mt*16 + gid;
                a[mt][0] = As[mr    ][ko+tig  ];
                a[mt][1] = As[mr + 8][ko+tig  ];
                a[mt][2] = As[mr    ][ko+tig+4];
                a[mt][3] = As[mr + 8][ko+tig+4];
            }
            #pragma unroll
            for (int nt=0;nt<4;nt++) {
                int nc = wn + nt*8 + gid;
                b[nt][0] = Bs[ko+tig  ][nc];
                b[nt][1] = Bs[ko+tig+4][nc];
            }
            #pragma unroll
            for (int mt=0;mt<4;mt++)
                #pragma unroll
                for (int nt=0;nt<4;nt++)
                    mma_tf32(c[mt][nt], a[mt], b[nt]);
        }
        __syncthreads();
    }

    #pragma unroll
    for (int nt=0;nt<4;nt++) {
        int col = n0 + wn + nt*8 + tig*2;
        float bv0 = bias[col], bv1 = bias[col+1];
        #pragma unroll
        for (int mt=0;mt<4;mt++) {
            int row = m0 + wm + mt*16 + gid;
            #pragma unroll
            for (int half=0; half<2; half++) {
                int r = row + half*8;
                float v0 = c[mt][nt][half*2+0] + bv0;
                float v1 = c[mt][nt][half*2+1] + bv1;
                if (MODE == 0) {
                    v0 = v0 / (1.f + __expf(-v0));
                    v1 = v1 / (1.f + __expf(-v1));
                }
                float2 o = make_float2(v0, v1);
                *(float2*)(C + (size_t)r*N + col) = o;
            }
        }
    }
}

// ---------------- blocked scan phase A: per-chunk weighted sums -------------
__global__ __launch_bounds__(128)
void k_chunkL() {
    int c = blockIdx.x, bh = blockIdx.y;
    int h = bh % NH_;
    int d = threadIdx.x;
    const float* Qc = g_Qh + ((size_t)bh*SEQ_ + c*CK_)*HD_;
    const float* gp = g_gpow + h*(SEQ_+1);
    float acc = 0.f;
    #pragma unroll 8
    for (int i = 0; i < CK_; i++)
        acc = fmaf(gp[i], Qc[(size_t)i*HD_ + d], acc);
    g_L[(bh*NC_ + c)*HD_ + d] = acc;
}

// ---------------- blocked scan phase B: cross-chunk carries -----------------
__global__ void k_carry() {
    int bh = blockIdx.x;
    int h = bh % NH_;
    int d = threadIdx.x;
    float g128 = g_gpow[h*(SEQ_+1) + CK_];
    float U = 0.f;
    for (int c = NC_-1; c >= 0; c--) {
        g_carry[(bh*NC_ + c)*HD_ + d] = U;
        U = fmaf(g128, U, g_L[(bh*NC_ + c)*HD_ + d]);
    }
}

// ---------------- blocked scan phase C: warp-per-chunk scan + coef ----------
__global__ __launch_bounds__(128)
void k_coef2() {
    int wid = threadIdx.x >> 5, lane = threadIdx.x & 31;
    int c = blockIdx.x * 4 + wid, bh = blockIdx.y;
    int h = bh % NH_;
    float gamma = 1.f - exp2f(-5.f - (float)h);
    const float* Qc  = g_Qh + ((size_t)bh*SEQ_ + c*CK_)*HD_;
    const float* rdp = g_rD + h*SEQ_ + c*CK_;
    float* cfp = g_coef + bh*SEQ_ + c*CK_;
    float4 u = *(const float4*)(g_carry + (bh*NC_ + c)*HD_ + lane*4);
    for (int r = CK_-1; r >= 0; r--) {
        float4 qv = *(const float4*)(Qc + (size_t)r*HD_ + lane*4);
        u.x = fmaf(gamma, u.x, qv.x);
        u.y = fmaf(gamma, u.y, qv.y);
        u.z = fmaf(gamma, u.z, qv.z);
        u.w = fmaf(gamma, u.w, qv.w);
        float p = qv.x*u.x + qv.y*u.y + qv.z*u.z + qv.w*u.w;
        #pragma unroll
        for (int o = 16; o; o >>= 1) p += __shfl_xor_sync(0xffffffffu, p, o);
        if (lane == 0) {
            float rd = rdp[r];
            float cs = rd * (p * SCALE_);
            cfp[r] = rd / fmaxf(fabsf(cs), 1.f);
        }
    }
}

// ---------------- per-chunk M_c = (w*Q)^T @ Q via double-TF32 mma ------------
#define CM_BYTES ((3*32*132)*4)
__global__ __launch_bounds__(256)
void k_chunkM() {
    extern __shared__ float smc[];
    float*    Qf = smc;                       // [32][132] fp32
    uint32_t* Bh = (uint32_t*)(smc + 32*132); // [32][132]
    uint32_t* Bl = Bh + 32*132;
    __shared__ float wk[32];

    const int c = blockIdx.x, bh = blockIdx.y;
    const int h = bh % NH_;
    const int t0 = c * CK_;
    const int tid = threadIdx.x;
    const int lane = tid & 31, wid = tid >> 5;
    const int gid = lane >> 2, tig = lane & 3;
    const int wm = (wid & 1) * 64, wn = (wid >> 1) * 32;

    const float* Qb = g_Qh + (size_t)bh*SEQ_*HD_;
    const float* gp = g_gpow + h*(SEQ_+1);
    const float* cf = g_coef + bh*SEQ_;

    float acc[4][4][4];
    #pragma unroll
    for (int mt=0;mt<4;mt++) for (int nt=0;nt<4;nt++) for (int r=0;r<4;r++) acc[mt][nt][r]=0.f;

    for (int k0 = 0; k0 < CK_; k0 += 32) {
        #pragma unroll
        for (int i = 0; i < 4; i++) {
            int idx = tid + i*256;
            int row = idx >> 5, c4 = (idx & 31) << 2;
            float4 v = *(const float4*)(Qb + (size_t)(t0+k0+row)*HD_ + c4);
            int base = row*132 + c4;
            Qf[base+0]=v.x; Qf[base+1]=v.y; Qf[base+2]=v.z; Qf[base+3]=v.w;
            uint32_t h0=f2tf(v.x), h1=f2tf(v.y), h2=f2tf(v.z), h3=f2tf(v.w);
            Bh[base+0]=h0; Bh[base+1]=h1; Bh[base+2]=h2; Bh[base+3]=h3;
            Bl[base+0]=f2tf_lo(v.x,h0); Bl[base+1]=f2tf_lo(v.y,h1);
            Bl[base+2]=f2tf_lo(v.z,h2); Bl[base+3]=f2tf_lo(v.w,h3);
        }
        if (tid < 32)
            wk[tid] = gp[CK_ - (k0+tid)] * SCALE_ * cf[t0 + k0 + tid];
        __syncthreads();
        #pragma unroll
        for (int k8 = 0; k8 < 4; k8++) {
            const int ko = k8*8;
            float w0 = wk[ko+tig], w1 = wk[ko+tig+4];
            uint32_t ah[4][4], al[4][4], bhf[4][2], blf[4][2];
            #pragma unroll
            for (int mt=0;mt<4;mt++) {
                int mr = wm + mt*16 + gid;
                float a0 = w0 * Qf[(ko+tig  )*132 + mr    ];
                float a1 = w0 * Qf[(ko+tig  )*132 + mr + 8];
                float a2 = w1 * Qf[(ko+tig+4)*132 + mr    ];
                float a3 = w1 * Qf[(ko+tig+4)*132 + mr + 8];
                ah[mt][0]=f2tf(a0); al[mt][0]=f2tf_lo(a0,ah[mt][0]);
                ah[mt][1]=f2tf(a1); al[mt][1]=f2tf_lo(a1,ah[mt][1]);
                ah[mt][2]=f2tf(a2); al[mt][2]=f2tf_lo(a2,ah[mt][2]);
                ah[mt][3]=f2tf(a3); al[mt][3]=f2tf_lo(a3,ah[mt][3]);
            }
            #pragma unroll
            for (int nt=0;nt<4;nt++) {
                int nc = wn + nt*8 + gid;
                bhf[nt][0] = Bh[(ko+tig)*132 + nc];
                bhf[nt][1] = Bh[(ko+tig+4)*132 + nc];
                blf[nt][0] = Bl[(ko+tig)*132 + nc];
                blf[nt][1] = Bl[(ko+tig+4)*132 + nc];
            }
            #pragma unroll
            for (int mt=0;mt<4;mt++)
                #pragma unroll
                for (int nt=0;nt<4;nt++)
                    mma_d2(acc[mt][nt], ah[mt], al[mt], bhf[nt], blf[nt]);
        }
        __syncthreads();
    }

    float* Mp = g_M + (size_t)(bh*NC_ + c)*HD_*HD_;
    #pragma unroll
    for (int nt=0;nt<4;nt++) {
        int col = wn + nt*8 + tig*2;
        #pragma unroll
        for (int mt=0;mt<4;mt++) {
            int row = wm + mt*16 + gid;
            *(float2*)(Mp + (size_t)row*HD_ + col)     = make_float2(acc[mt][nt][0], acc[mt][nt][1]);
            *(float2*)(Mp + (size_t)(row+8)*HD_ + col) = make_float2(acc[mt][nt][2], acc[mt][nt][3]);
        }
    }
}

// ---------------- state: S_c = sum_{j<c} g128^(c-1-j) * M_j (parallel) -------
__global__ __launch_bounds__(256)
void k_state() {
    int c = blockIdx.x, bh = blockIdx.y;
    int h = bh % NH_;
    float g128 = g_gpow[h*(SEQ_+1) + CK_];
    int tid = threadIdx.x;
    float4 acc[16];
    #pragma unroll
    for (int i=0;i<16;i++) acc[i] = make_float4(0.f,0.f,0.f,0.f);
    for (int j = 0; j < c; j++) {
        const float4* m = (const float4*)(g_M + (size_t)(bh*NC_ + j)*HD_*HD_);
        #pragma unroll
        for (int i=0;i<16;i++) {
            float4 mv = m[tid + i*256];
            acc[i].x = fmaf(g128, acc[i].x, mv.x);
            acc[i].y = fmaf(g128, acc[i].y, mv.y);
            acc[i].z = fmaf(g128, acc[i].z, mv.z);
            acc[i].w = fmaf(g128, acc[i].w, mv.w);
        }
    }
    float4* dst = (float4*)(g_S + (size_t)(bh*NC_ + c)*HD_*HD_);
    #pragma unroll
    for (int i=0;i<16;i++) dst[tid + i*256] = acc[i];
}

// ---------------- chunkwise output pass: double-TF32 tensor cores -----------
// O = masked-decayed(Q@Q^T)@Q + diag(gamma^r)*(Q@S_c)
#define SM2_BYTES ((3*128*132)*4)
__global__ __launch_bounds__(256, 1)
void k_pass2ck() {
    extern __shared__ float smf[];
    uint32_t* Qhi = (uint32_t*)smf;           // [128][132]
    uint32_t* Qlo = Qhi + 128*132;            // [128][132]
    float*    Ps  = smf + 2*128*132;          // [128][132] fp32 P; reused in stage d
    uint32_t* Shi = (uint32_t*)Ps;            // stage d: [32][132]
    uint32_t* Slo = Shi + 32*132;

    const int tid = threadIdx.x;
    const int lane = tid & 31, wid = tid >> 5;
    const int gid = lane >> 2, tig = lane & 3;
    const int wm = (wid & 1) * 64, wn = (wid >> 1) * 32;
    const int c = blockIdx.x, bh = blockIdx.y;
    const int s0 = c * CK_;
    const int h = bh % NH_;
    const float* Qb = g_Qh + ((size_t)bh*SEQ_ + s0)*HD_;
    const float* gp = g_gpow + h*(SEQ_+1);
    const float* cf = g_coef + bh*SEQ_ + s0;
    const float* Sc = g_S + (size_t)(bh*NC_ + c)*HD_*HD_;

    // load Q chunk -> hi/lo tiles
    #pragma unroll
    for (int i = 0; i < 16; i++) {
        int idx = tid + i*256;
        int row = idx >> 5, c4 = (idx & 31) << 2;
        float4 v = *(const float4*)(Qb + (size_t)row*HD_ + c4);
        int base = row*132 + c4;
        uint32_t h0=f2tf(v.x), h1=f2tf(v.y), h2=f2tf(v.z), h3=f2tf(v.w);
        Qhi[base+0]=h0; Qhi[base+1]=h1; Qhi[base+2]=h2; Qhi[base+3]=h3;
        Qlo[base+0]=f2tf_lo(v.x,h0); Qlo[base+1]=f2tf_lo(v.y,h1);
        Qlo[base+2]=f2tf_lo(v.z,h2); Qlo[base+3]=f2tf_lo(v.w,h3);
    }
    __syncthreads();

    // per-thread decay constants
    float rowg[8];
    #pragma unroll
    for (int mt=0;mt<4;mt++) {
        rowg[mt*2+0] = gp[wm + mt*16 + gid];
        rowg[mt*2+1] = gp[wm + mt*16 + gid + 8];
    }
    float colinv[8], cfv[8];
    #pragma unroll
    for (int nt=0;nt<4;nt++) {
        int col0 = wn + nt*8 + tig*2;
        colinv[nt*2+0] = 1.f / gp[col0];
        colinv[nt*2+1] = 1.f / gp[col0+1];
        cfv[nt*2+0] = cf[col0];
        cfv[nt*2+1] = cf[col0+1];
    }

    // ---- stage a: S = Q@Q^T ----
    float Sf[4][4][4];
    #pragma unroll
    for (int mt=0;mt<4;mt++) for (int nt=0;nt<4;nt++) for (int r=0;r<4;r++) Sf[mt][nt][r]=0.f;
    #pragma unroll 4
    for (int k8 = 0; k8 < 16; k8++) {
        const int ko = k8*8;
        uint32_t ah[4][4], al[4][4], bhf[4][2], blf[4][2];
        #pragma unroll
        for (int mt=0;mt<4;mt++) {
            int mr = wm + mt*16 + gid;
            ah[mt][0]=Qhi[mr*132+ko+tig];     al[mt][0]=Qlo[mr*132+ko+tig];
            ah[mt][1]=Qhi[(mr+8)*132+ko+tig]; al[mt][1]=Qlo[(mr+8)*132+ko+tig];
            ah[mt][2]=Qhi[mr*132+ko+tig+4];   al[mt][2]=Qlo[mr*132+ko+tig+4];
            ah[mt][3]=Qhi[(mr+8)*132+ko+tig+4];al[mt][3]=Qlo[(mr+8)*132+ko+tig+4];
        }
        #pragma unroll
        for (int nt=0;nt<4;nt++) {
            int nc = wn + nt*8 + gid;
            bhf[nt][0]=Qhi[nc*132+ko+tig];   blf[nt][0]=Qlo[nc*132+ko+tig];
            bhf[nt][1]=Qhi[nc*132+ko+tig+4]; blf[nt][1]=Qlo[nc*132+ko+tig+4];
        }
        #pragma unroll
        for (int mt=0;mt<4;mt++)
            #pragma unroll
            for (int nt=0;nt<4;nt++)
                mma_d2(Sf[mt][nt], ah[mt], al[mt], bhf[nt], blf[nt]);
    }

    // ---- stage b: apply mask/decay/coef, write P fp32 to smem ----
    #pragma unroll
    for (int mt=0;mt<4;mt++) {
        #pragma unroll
        for (int nt=0;nt<4;nt++) {
            #pragma unroll
            for (int r=0;r<4;r++) {
                int rw = wm + mt*16 + gid + (r>>1)*8;
                int cl = wn + nt*8 + tig*2 + (r&1);
                float w = (rw >= cl) ? (SCALE_ * rowg[mt*2+(r>>1)] * colinv[nt*2+(r&1)] * cfv[nt*2+(r&1)]) : 0.f;
                Ps[rw*132 + cl] = Sf[mt][nt][r] * w;
            }
        }
    }
    __syncthreads();

    // ---- stage c: O1 = P @ Q (on-the-fly split of P) ----
    float O1[4][4][4];
    #pragma unroll
    for (int mt=0;mt<4;mt++) for (int nt=0;nt<4;nt++) for (int r=0;r<4;r++) O1[mt][nt][r]=0.f;
    #pragma unroll 4
    for (int k8 = 0; k8 < 16; k8++) {
        const int ko = k8*8;
        uint32_t ah[4][4], al[4][4], bhf[4][2], blf[4][2];
        #pragma unroll
        for (int mt=0;mt<4;mt++) {
            int mr = wm + mt*16 + gid;
            float p0 = Ps[mr*132+ko+tig];
            float p1 = Ps[(mr+8)*132+ko+tig];
            float p2 = Ps[mr*132+ko+tig+4];
            float p3 = Ps[(mr+8)*132+ko+tig+4];
            ah[mt][0]=f2tf(p0); al[mt][0]=f2tf_lo(p0,ah[mt][0]);
            ah[mt][1]=f2tf(p1); al[mt][1]=f2tf_lo(p1,ah[mt][1]);
            ah[mt][2]=f2tf(p2); al[mt][2]=f2tf_lo(p2,ah[mt][2]);
            ah[mt][3]=f2tf(p3); al[mt][3]=f2tf_lo(p3,ah[mt][3]);
        }
        #pragma unroll
        for (int nt=0;nt<4;nt++) {
            int nc = wn + nt*8 + gid;
            bhf[nt][0]=Qhi[(ko+tig)*132+nc];   blf[nt][0]=Qlo[(ko+tig)*132+nc];
            bhf[nt][1]=Qhi[(ko+tig+4)*132+nc]; blf[nt][1]=Qlo[(ko+tig+4)*132+nc];
        }
        #pragma unroll
        for (int mt=0;mt<4;mt++)
            #pragma unroll
            for (int nt=0;nt<4;nt++)
                mma_d2(O1[mt][nt], ah[mt], al[mt], bhf[nt], blf[nt]);
    }
    __syncthreads();   // Ps reads done; safe to reuse region for S chunks

    // ---- stage d: O2 = Q @ S_c (k-chunked S staging into reused smem) ----
    float O2[4][4][4];
    #pragma unroll
    for (int mt=0;mt<4;mt++) for (int nt=0;nt<4;nt++) for (int r=0;r<4;r++) O2[mt][nt][r]=0.f;
    for (int k0 = 0; k0 < HD_; k0 += 32) {
        #pragma unroll
        for (int i = 0; i < 4; i++) {
            int idx = tid + i*256;
            int row = idx >> 5, c4 = (idx & 31) << 2;
            float4 v = *(const float4*)(Sc + (size_t)(k0+row)*HD_ + c4);
            int base = row*132 + c4;
            uint32_t h0=f2tf(v.x), h1=f2tf(v.y), h2=f2tf(v.z), h3=f2tf(v.w);
            Shi[base+0]=h0; Shi[base+1]=h1; Shi[base+2]=h2; Shi[base+3]=h3;
            Slo[base+0]=f2tf_lo(v.x,h0); Slo[base+1]=f2tf_lo(v.y,h1);
            Slo[base+2]=f2tf_lo(v.z,h2); Slo[base+3]=f2tf_lo(v.w,h3);
        }
        __syncthreads();
        #pragma unroll
        for (int k8 = 0; k8 < 4; k8++) {
            const int ko = k8*8;
            uint32_t ah[4][4], al[4][4], bhf[4][2], blf[4][2];
            #pragma unroll
            for (int mt=0;mt<4;mt++) {
                int mr = wm + mt*16 + gid;
                ah[mt][0]=Qhi[mr*132+k0+ko+tig];      al[mt][0]=Qlo[mr*132+k0+ko+tig];
                ah[mt][1]=Qhi[(mr+8)*132+k0+ko+tig];  al[mt][1]=Qlo[(mr+8)*132+k0+ko+tig];
                ah[mt][2]=Qhi[mr*132+k0+ko+tig+4];    al[mt][2]=Qlo[mr*132+k0+ko+tig+4];
                ah[mt][3]=Qhi[(mr+8)*132+k0+ko+tig+4];al[mt][3]=Qlo[(mr+8)*132+k0+ko+tig+4];
            }
            #pragma unroll
            for (int nt=0;nt<4;nt++) {
                int nc = wn + nt*8 + gid;
                bhf[nt][0]=Shi[(ko+tig)*132+nc];   blf[nt][0]=Slo[(ko+tig)*132+nc];
                bhf[nt][1]=Shi[(ko+tig+4)*132+nc]; blf[nt][1]=Slo[(ko+tig+4)*132+nc];
            }
            #pragma unroll
            for (int mt=0;mt<4;mt++)
                #pragma unroll
                for (int nt=0;nt<4;nt++)
                    mma_d2(O2[mt][nt], ah[mt], al[mt], bhf[nt], blf[nt]);
        }
        __syncthreads();
    }

    // ---- epilogue: out = O1 + gamma^row * O2 ----
    float* outp = g_ho + ((size_t)bh*SEQ_ + s0)*HD_;
    #pragma unroll
    for (int nt=0;nt<4;nt++) {
        int col = wn + nt*8 + tig*2;
        #pragma unroll
        for (int mt=0;mt<4;mt++) {
            int row = wm + mt*16 + gid;
            float g0 = rowg[mt*2+0], g1 = rowg[mt*2+1];
            float2 o0 = make_float2(O1[mt][nt][0] + g0*O2[mt][nt][0],
                                    O1[mt][nt][1] + g0*O2[mt][nt][1]);
            float2 o1 = make_float2(O1[mt][nt][2] + g1*O2[mt][nt][2],
                                    O1[mt][nt][3] + g1*O2[mt][nt][3]);
            *(float2*)(outp + (size_t)row*HD_ + col)     = o0;
            *(float2*)(outp + (size_t)(row+8)*HD_ + col) = o1;
        }
    }
}

// ---------------- GroupNorm(32 groups) + beta, then gate --------------------
__global__ __launch_bounds__(256)
void k_gn(const float* __restrict__ beta) {
    int row = blockIdx.x;
    int b = row >> 11, s = row & (SEQ_-1);
    int tid = threadIdx.x;
    int c = tid << 2;
    int h = c >> 7, d = c & 127;
    float4 x = *(const float4*)(g_ho + (((size_t)(b*NH_+h)*SEQ_ + s)*HD_ + d));

    float sum = x.x + x.y + x.z + x.w;
    #pragma unroll
    for (int o = 1; o < 8; o <<= 1) sum += __shfl_xor_sync(0xffffffffu, sum, o);
    float mu = sum * (1.f/32.f);

    float dx0 = x.x-mu, dx1 = x.y-mu, dx2 = x.z-mu, dx3 = x.w-mu;
    float sq = dx0*dx0 + dx1*dx1 + dx2*dx2 + dx3*dx3;
    #pragma unroll
    for (int o = 1; o < 8; o <<= 1) sq += __shfl_xor_sync(0xffffffffu, sq, o);
    float inv = rsqrtf(sq * (1.f/32.f) + 1e-3f);

    float4 be = *(const float4*)(beta + c);
    float4 g  = *(const float4*)(g_gate + (size_t)row*DIM_ + c);
    float4 z;
    z.x = (dx0*inv + be.x) * g.x;
    z.y = (dx1*inv + be.y) * g.y;
    z.z = (dx2*inv + be.z) * g.z;
    z.w = (dx3*inv + be.w) * g.w;
    *(float4*)(g_Z + (size_t)row*DIM_ + c) = z;
}

// ---------------- launch ----------------------------------------------------
extern "C" void kernel_launch(void* const* d_in, const int* in_sizes, int n_in,
                              void* d_out, int out_size) {
    (void)in_sizes; (void)n_in; (void)out_size;
    const float* q    = (const float*)d_in[0];
    const float* Wqkv = (const float*)d_in[3];
    const float* Wg   = (const float*)d_in[4];
    const float* bg   = (const float*)d_in[5];
    const float* Wo   = (const float*)d_in[6];
    const float* bo   = (const float*)d_in[7];
    const float* beta = (const float*)d_in[8];
    float* out = (float*)d_out;

    float *p_gate = nullptr, *p_Z = nullptr;
    cudaGetSymbolAddress((void**)&p_gate, g_gate);
    cudaGetSymbolAddress((void**)&p_Z,    g_Z);
    cudaFuncSetAttribute(k_pass2ck, cudaFuncAttributeMaxDynamicSharedMemorySize, SM2_BYTES);
    cudaFuncSetAttribute(k_chunkM,  cudaFuncAttributeMaxDynamicSharedMemorySize, CM_BYTES);

    k_decay<<<NH_, 256>>>();
    k_proj<<<dim3(SEQ_/64, B_*NH_), 256>>>(q, Wqkv);
    k_gemm_tc<0><<<dim3(DIM_/128, B_*SEQ_/128), 256>>>(q, Wg, bg, p_gate);
    k_chunkL<<<dim3(NC_, B_*NH_), HD_>>>();
    k_carry<<<B_*NH_, HD_>>>();
    k_coef2<<<dim3(NC_/4, B_*NH_), 128>>>();
    k_chunkM<<<dim3(NC_, B_*NH_), 256, CM_BYTES>>>();
    k_state<<<dim3(NC_, B_*NH_), 256>>>();
    k_pass2ck<<<dim3(NC_, B_*NH_), 256, SM2_BYTES>>>();
    k_gn<<<B_*SEQ_, 256>>>(beta);
    k_gemm_tc<1><<<dim3(DIM_/128, B_*SEQ_/128), 256>>>(p_Z, Wo, bo, out);
}